// round 12
// baseline (speedup 1.0000x reference)
#include <cuda_runtime.h>
#include <math.h>
#include <stdint.h>

#define BATCH 16
#define H 1024
#define W 1024
#define HW (H * W)
#define NB 65536
#define NSAMP 65536
#define TWO_PI_F 6.28318530717958647692f
#define STEP_F 0.78539816339744830962f
#define EPSV 1e-6f

__constant__ int c_ranks[4] = {20971, 20972, 1027603, 1027604};
__constant__ int c_wrank[4] = {968, 1653, 63883, 64567};

// ---------------- device scratch ----------------
__device__ unsigned g_qh[BATCH][2][NB];
__device__ unsigned g_below[BATCH][2];
__device__ float    g_slo[BATCH][2];
__device__ float    g_shi[BATCH][2];
__device__ float    g_sinv[BATCH][2];
__device__ float    g_sbw[BATCH][2];
__device__ int      g_merged[BATCH];
__device__ int      g_fail[BATCH];
__device__ float    g_lo[BATCH];
__device__ float    g_den[BATCH];
__device__ float    g_qval[BATCH][4];

__constant__ int c_dy[8] = {0, -1, -1, -1, 0, 1, 1, 1};
__constant__ int c_dx[8] = {1, 1, 0, -1, -1, -1, 0, 1};

__device__ __forceinline__ unsigned f2key(float f) {
    unsigned u = __float_as_uint(f);
    return (u & 0x80000000u) ? ~u : (u | 0x80000000u);
}
__device__ __forceinline__ float key2f(unsigned k) {
    unsigned u = (k & 0x80000000u) ? (k & 0x7fffffffu) : ~k;
    return __uint_as_float(u);
}
__device__ __forceinline__ int sample_idx(int i) {
    int chunk = i >> 6;
    int off = (chunk * 7919) & 960;
    return (chunk << 10) + off + (i & 63);
}

__device__ __forceinline__ int warp_walk_tot(const unsigned* hist, int nb, int& rank, unsigned& total) {
    int lane = threadIdx.x & 31;
    int chunk = nb / 32;
    const unsigned* hc = hist + lane * chunk;
    unsigned s = 0;
    for (int j = 0; j < chunk; j++) s += hc[j];
    unsigned inc = s;
#pragma unroll
    for (int o = 1; o < 32; o <<= 1) {
        unsigned v = __shfl_up_sync(0xffffffffu, inc, o);
        if (lane >= o) inc += v;
    }
    total = __shfl_sync(0xffffffffu, inc, 31);
    unsigned ex = inc - s;
    unsigned ball = __ballot_sync(0xffffffffu, (int)ex <= rank);
    int sel = 31 - __clz(ball);
    int d = 0, r = rank;
    if (lane == sel) {
        r = rank - (int)ex;
        d = lane * chunk;
        for (int j = 0; j < chunk; j++) {
            unsigned c = hc[j];
            if (r < (int)c) { d = lane * chunk + j; break; }
            r -= (int)c;
        }
    }
    d = __shfl_sync(0xffffffffu, d, sel);
    r = __shfl_sync(0xffffffffu, r, sel);
    rank = r;
    return d;
}

// ---------------- sampled bounds + init (one block per batch) ----------------
__global__ __launch_bounds__(1024) void k_bounds(const float* __restrict__ x) {
    __shared__ unsigned h[8192];
    __shared__ float red[64];
    __shared__ int sb[4];
    __shared__ float s_mn, s_scale;
    int b = blockIdx.x;
    const float* xb = x + (size_t)b * HW;
    int tid = threadIdx.x;

    for (int i = tid; i < 2 * NB; i += 1024) (&g_qh[b][0][0])[i] = 0u;
    if (tid < 2) g_below[b][tid] = 0u;
    if (tid == 0) g_fail[b] = 0;

    float mn = __int_as_float(0x7f800000), mx = -mn;
    for (int i = tid; i < NSAMP; i += 1024) {
        float v = xb[sample_idx(i)];
        mn = fminf(mn, v); mx = fmaxf(mx, v);
    }
#pragma unroll
    for (int o = 16; o > 0; o >>= 1) {
        mn = fminf(mn, __shfl_down_sync(0xffffffffu, mn, o));
        mx = fmaxf(mx, __shfl_down_sync(0xffffffffu, mx, o));
    }
    int w = tid >> 5;
    if ((tid & 31) == 0) { red[w] = mn; red[32 + w] = mx; }
    __syncthreads();
    if (tid == 0) {
        float m0 = red[0], m1 = red[32];
        for (int i = 1; i < 32; i++) { m0 = fminf(m0, red[i]); m1 = fmaxf(m1, red[32 + i]); }
        s_mn = m0;
        float span = m1 - m0;
        s_scale = (span > 1e-20f) ? 8192.0f / span : -1.0f;
    }
    for (int i = tid; i < 8192; i += 1024) h[i] = 0u;
    __syncthreads();
    float smn = s_mn, sscale = s_scale;
    if (sscale < 0.f) {
        if (tid == 0) {
            g_fail[b] = 1;
            float inf = __int_as_float(0x7f800000);
            g_slo[b][0] = inf; g_shi[b][0] = inf;
            g_slo[b][1] = inf; g_shi[b][1] = inf;
        }
        return;
    }
    float bw8 = 1.0f / sscale;

    for (int i = tid; i < NSAMP; i += 1024) {
        float v = xb[sample_idx(i)];
        int bin = (int)((v - smn) * sscale);
        atomicAdd(&h[min(max(bin, 0), 8191)], 1u);
    }
    __syncthreads();
    if (w < 4) {
        int r = c_wrank[w];
        unsigned tot;
        int d = warp_walk_tot(h, 8192, r, tot);
        if ((tid & 31) == 0) sb[w] = d;
    }
    __syncthreads();
    if (tid == 0) {
        float inf = __int_as_float(0x7f800000);
        float l0 = smn + (float)(sb[0] - 1) * bw8;
        float h0 = smn + (float)(sb[1] + 2) * bw8;
        float l1 = smn + (float)(sb[2] - 1) * bw8;
        float h1 = smn + (float)(sb[3] + 2) * bw8;
        int merged = (l1 <= h0);
        if (merged) { h0 = h1; l1 = inf; h1 = inf; }
        g_merged[b] = merged;
        g_slo[b][0] = l0; g_shi[b][0] = h0;
        g_sinv[b][0] = (float)NB / (h0 - l0);
        g_sbw[b][0] = (h0 - l0) / (float)NB;
        g_slo[b][1] = l1; g_shi[b][1] = h1;
        if (!merged) {
            g_sinv[b][1] = (float)NB / (h1 - l1);
            g_sbw[b][1] = (h1 - l1) / (float)NB;
        } else {
            g_sinv[b][1] = 0.f; g_sbw[b][1] = 0.f;
        }
    }
}

// ---------------- one full scan: below-counts + bracketed value histogram ----------------
__global__ __launch_bounds__(256) void k_qhist(const float* __restrict__ x) {
    int b = blockIdx.y;
    float l0 = g_slo[b][0], h0 = g_shi[b][0], inv0 = g_sinv[b][0];
    float l1 = g_slo[b][1], h1 = g_shi[b][1], inv1 = g_sinv[b][1];
    unsigned* hist0 = g_qh[b][0];
    unsigned* hist1 = g_qh[b][1];
    unsigned below0 = 0, below1 = 0;

    const float4* xb = (const float4*)(x + (size_t)b * HW);
    const int nvec = HW / 4;
    for (int i = blockIdx.x * blockDim.x + threadIdx.x; i < nvec; i += gridDim.x * blockDim.x) {
        float4 v4 = xb[i];
        float vs[4] = {v4.x, v4.y, v4.z, v4.w};
#pragma unroll
        for (int e = 0; e < 4; e++) {
            float v = vs[e];
            below0 += (v < l0);
            below1 += (v < l1);
            if (v >= l0 && v < h0) {
                int bin = (int)((v - l0) * inv0);
                atomicAdd(&hist0[min(bin, NB - 1)], 1u);
            } else if (v >= l1 && v < h1) {
                int bin = (int)((v - l1) * inv1);
                atomicAdd(&hist1[min(bin, NB - 1)], 1u);
            }
        }
    }
#pragma unroll
    for (int o = 16; o > 0; o >>= 1) {
        below0 += __shfl_down_sync(0xffffffffu, below0, o);
        below1 += __shfl_down_sync(0xffffffffu, below1, o);
    }
    if ((threadIdx.x & 31) == 0) {
        atomicAdd(&g_below[b][0], below0);
        atomicAdd(&g_below[b][1], below1);
    }
}

// ---------------- finalize: block-parallel interpolating walk ----------------
#define QCHUNK (NB / 256)
__global__ __launch_bounds__(512) void k_qfinal() {
    int b = blockIdx.x;
    if (g_fail[b]) return;
    __shared__ unsigned sums[2][256];
    __shared__ float qres[2];
    __shared__ int sfail;
    int tid = threadIdx.x;
    int hh = tid >> 8;
    int t = tid & 255;
    if (tid == 0) sfail = 0;
    int merged = g_merged[b];
    int slot = (hh == 0) ? 0 : (merged ? 0 : 1);
    int K = (hh == 0) ? 20971 : 1027603;
    const unsigned* hist = g_qh[b][slot];

    unsigned s = 0;
#pragma unroll 8
    for (int j = 0; j < QCHUNK; j++) s += hist[t * QCHUNK + j];
    sums[hh][t] = s;
    __syncthreads();
    for (int o = 1; o < 256; o <<= 1) {
        unsigned v = (t >= o) ? sums[hh][t - o] : 0u;
        __syncthreads();
        sums[hh][t] += v;
        __syncthreads();
    }
    unsigned inc = sums[hh][t];
    unsigned ex = inc - s;
    unsigned total = sums[hh][255];
    int r = K - (int)g_below[b][slot];
    if (r < 0 || (unsigned)r >= total) {
        if (t == 0) sfail = 1;
    } else if ((int)ex <= r && r < (int)inc) {
        int rr = r - (int)ex;
        int d = t * QCHUNK;
        unsigned n = 0;
        for (int j = 0; j < QCHUNK; j++) {
            unsigned c = hist[t * QCHUNK + j];
            if (rr < (int)c) { d = t * QCHUNK + j; n = c; break; }
            rr -= (int)c;
        }
        qres[hh] = g_slo[b][slot] + ((float)d + ((float)rr + 1.0f) / (float)n) * g_sbw[b][slot];
    }
    __syncthreads();
    if (tid == 0) {
        if (sfail) g_fail[b] = 1;
        else {
            float lo = qres[0], hi = qres[1];
            g_lo[b] = lo;
            g_den[b] = hi - lo + EPSV;
        }
    }
}

// ---------------- rescue: full exact per-batch select (gated; normally no-op) ----------------
__global__ void k_rescue(const float* __restrict__ x) {
    int b = blockIdx.x;
    if (!g_fail[b]) return;
    __shared__ unsigned h[8192];
    __shared__ int sbin[4], sd2[4], srnk[4];
    const float* xb = x + (size_t)b * HW;

    for (int i = threadIdx.x; i < 8192; i += blockDim.x) h[i] = 0u;
    __syncthreads();
    for (int i = threadIdx.x; i < HW; i += blockDim.x)
        atomicAdd(&h[f2key(xb[i]) >> 19], 1u);
    __syncthreads();
    int w = threadIdx.x >> 5;
    if (w < 4) {
        int r = c_ranks[w];
        unsigned tot;
        int d = warp_walk_tot(h, 8192, r, tot);
        if ((threadIdx.x & 31) == 0) { sbin[w] = d; srnk[w] = r; }
    }
    __syncthreads();
    for (int t = 0; t < 4; t++) {
        for (int i = threadIdx.x; i < 2048; i += blockDim.x) h[i] = 0u;
        __syncthreads();
        unsigned tb = (unsigned)sbin[t];
        for (int i = threadIdx.x; i < HW; i += blockDim.x) {
            unsigned k = f2key(xb[i]);
            if ((k >> 19) == tb) atomicAdd(&h[(k >> 8) & 2047u], 1u);
        }
        __syncthreads();
        if (w == 0) {
            int r = srnk[t];
            unsigned tot;
            int d = warp_walk_tot(h, 2048, r, tot);
            if ((threadIdx.x & 31) == 0) { sd2[t] = d; srnk[t] = r; }
        }
        __syncthreads();
    }
    for (int t = 0; t < 4; t++) {
        for (int i = threadIdx.x; i < 256; i += blockDim.x) h[i] = 0u;
        __syncthreads();
        unsigned pre = ((unsigned)sbin[t] << 11) | (unsigned)sd2[t];
        for (int i = threadIdx.x; i < HW; i += blockDim.x) {
            unsigned k = f2key(xb[i]);
            if ((k >> 8) == pre) atomicAdd(&h[k & 255u], 1u);
        }
        __syncthreads();
        if (w == 0) {
            int r = srnk[t];
            unsigned tot;
            int d = warp_walk_tot(h, 256, r, tot);
            if ((threadIdx.x & 31) == 0)
                g_qval[b][t] = key2f(((unsigned)sbin[t] << 19) | ((unsigned)sd2[t] << 8) | (unsigned)d);
        }
        __syncthreads();
    }
    if (threadIdx.x == 0) {
        float q0 = g_qval[b][0], q1 = g_qval[b][1];
        float q2 = g_qval[b][2], q3 = g_qval[b][3];
        float lo = q0 + 0.5f * (q1 - q0);
        float hi = q2 + 0.5f * (q3 - q2);
        g_lo[b] = lo;
        g_den[b] = hi - lo + EPSV;
    }
}

// ---------------- fused: normalize + sobel + octant + dir-max + end map (64x64) ----------------
#define TS 64
#define HALO 6
#define SW (TS + 2 * HALO)   // 76
#define SPITCH (SW + 1)      // 77

__global__ __launch_bounds__(512) void k_fused(const float* __restrict__ x,
                                               float* __restrict__ emap,
                                               float* __restrict__ binsf,
                                               float* __restrict__ xnout) {
    __shared__ float tile[SW * SPITCH];
    int b = blockIdx.z;
    int bx = blockIdx.x * TS, by = blockIdx.y * TS;
    const float* xb = x + (size_t)b * HW;
    int tid = threadIdx.x;
    int l64 = tid & 63;
    int grp = tid >> 6;   // 0..7

    float lo = g_lo[b];
    float den = g_den[b];

    bool interior = (bx >= HALO) && (bx + TS + HALO <= W) && (by >= HALO) && (by + TS + HALO <= H);
    if (interior) {
        const float* src = xb + (size_t)(by - HALO) * W + (bx - HALO);
        for (int r = grp; r < SW; r += 8) {
            const float* row = src + r * W;
            float* trow = &tile[r * SPITCH];
            for (int c = l64; c < SW; c += 64)
                trow[c] = fminf(fmaxf((row[c] - lo) / den, 0.f), 1.f);
        }
    } else {
        for (int r = grp; r < SW; r += 8) {
            int gy = by + r - HALO;
            float* trow = &tile[r * SPITCH];
            for (int c = l64; c < SW; c += 64) {
                int gx = bx + c - HALO;
                float v = 0.f;
                if ((unsigned)gy < H && (unsigned)gx < W)
                    v = fminf(fmaxf((xb[gy * W + gx] - lo) / den, 0.f), 1.f);
                trow[c] = v;
            }
        }
    }
    __syncthreads();

    // 8 consecutive rows per thread; roll sobel stencil rows through registers
    int tx = l64 + HALO;
    int ty0 = grp * 8 + HALO;
    float p00 = tile[(ty0 - 1) * SPITCH + tx - 1];
    float p01 = tile[(ty0 - 1) * SPITCH + tx];
    float p02 = tile[(ty0 - 1) * SPITCH + tx + 1];
    float p10 = tile[ty0 * SPITCH + tx - 1];
    float p11 = tile[ty0 * SPITCH + tx];
    float p12 = tile[ty0 * SPITCH + tx + 1];

#pragma unroll
    for (int k = 0; k < 8; k++) {
        int ty = ty0 + k;
        const float* rnext = &tile[(ty + 1) * SPITCH + tx];
        float p20 = rnext[-1], p21 = rnext[0], p22 = rnext[1];

        float gxs = (p02 - p00) + 2.f * (p12 - p10) + (p22 - p20);
        float gys = (p20 - p00) + 2.f * (p21 - p01) + (p22 - p02);

        // branchless exact octant of atan2(gys,gxs) mod 2pi in pi/4 bins
        // (boundary/tie behavior verified against atan2f float rounding)
        int bin = (gxs > 0.f && gys >= 0.f) ? ((gys < gxs) ? 0 : 1)
                : (gys > 0.f)               ? ((-gxs < gys) ? 2 : 3)
                : (gxs < 0.f)               ? ((-gys < -gxs) ? 4 : 5)
                : (gys < 0.f)               ? ((gxs < -gys) ? 6 : 7)
                : 0;
        int b8 = (bin + 2) & 7;

        const float* t0 = &tile[ty * SPITCH + tx];
        int step = c_dy[b8] * SPITCH + c_dx[b8];
        float f = 0.f, w = 0.f;
#pragma unroll
        for (int r = 1; r <= 6; r++) {
            f = fmaxf(f, t0[-step * r]);
            w = fmaxf(w, t0[ step * r]);
        }
        float mn = fminf(f, w), mx = fmaxf(f, w);
        float ratio = __fdividef(mn, mx + EPSV);
        float x0 = p11;
        float em = fminf(fmaxf(x0 * (1.f - ratio), 0.f), 1.f);

        size_t o = (size_t)b * HW + (size_t)(by + grp * 8 + k) * W + (bx + l64);
        __stcs(&emap[o], em);
        if (binsf) __stcs(&binsf[o], (float)b8);
        if (xnout) __stcs(&xnout[o], x0);

        p00 = p10; p01 = p11; p02 = p12;
        p10 = p20; p11 = p21; p12 = p22;
    }
}

// ---------------- launch ----------------
extern "C" void kernel_launch(void* const* d_in, const int* in_sizes, int n_in,
                              void* d_out, int out_size) {
    const float* x = (const float*)d_in[0];
    float* out = (float*)d_out;
    const size_t N = (size_t)BATCH * HW;

    float* emap  = out;
    float* binsf = ((size_t)out_size >= 2 * N) ? out + N : nullptr;
    float* xnout = ((size_t)out_size >= 3 * N) ? out + 2 * N : nullptr;

    k_bounds<<<BATCH, 1024>>>(x);
    k_qhist<<<dim3(64, BATCH), 256>>>(x);
    k_qfinal<<<BATCH, 512>>>();
    k_rescue<<<BATCH, 256>>>(x);

    dim3 gf(W / TS, H / TS, BATCH);
    k_fused<<<gf, 512>>>(x, emap, binsf, xnout);
}

// round 13
// speedup vs baseline: 1.2729x; 1.2729x over previous
#include <cuda_runtime.h>
#include <math.h>
#include <stdint.h>

#define BATCH 16
#define H 1024
#define W 1024
#define HW (H * W)
#define NB 16384
#define NSAMP 65536
#define TWO_PI_F 6.28318530717958647692f
#define STEP_F 0.78539816339744830962f
#define EPSV 1e-6f

__constant__ int c_ranks[4] = {20971, 20972, 1027603, 1027604};
__constant__ int c_wrank[4] = {968, 1653, 63883, 64567};

// ---------------- device scratch ----------------
__device__ unsigned g_qh[BATCH][2][NB];
__device__ unsigned g_below[BATCH][2];
__device__ float    g_slo[BATCH][2];
__device__ float    g_shi[BATCH][2];
__device__ float    g_sinv[BATCH][2];
__device__ float    g_sbw[BATCH][2];
__device__ int      g_merged[BATCH];
__device__ int      g_fail[BATCH];
__device__ float    g_lo[BATCH];
__device__ float    g_den[BATCH];
__device__ float    g_qval[BATCH][4];

__constant__ int c_dy[8] = {0, -1, -1, -1, 0, 1, 1, 1};
__constant__ int c_dx[8] = {1, 1, 0, -1, -1, -1, 0, 1};

__device__ __forceinline__ unsigned f2key(float f) {
    unsigned u = __float_as_uint(f);
    return (u & 0x80000000u) ? ~u : (u | 0x80000000u);
}
__device__ __forceinline__ float key2f(unsigned k) {
    unsigned u = (k & 0x80000000u) ? (k & 0x7fffffffu) : ~k;
    return __uint_as_float(u);
}
__device__ __forceinline__ int sample_idx(int i) {
    int chunk = i >> 6;
    int off = (chunk * 7919) & 960;
    return (chunk << 10) + off + (i & 63);
}

__device__ __forceinline__ int warp_walk_tot(const unsigned* hist, int nb, int& rank, unsigned& total) {
    int lane = threadIdx.x & 31;
    int chunk = nb / 32;
    const unsigned* hc = hist + lane * chunk;
    unsigned s = 0;
    for (int j = 0; j < chunk; j++) s += hc[j];
    unsigned inc = s;
#pragma unroll
    for (int o = 1; o < 32; o <<= 1) {
        unsigned v = __shfl_up_sync(0xffffffffu, inc, o);
        if (lane >= o) inc += v;
    }
    total = __shfl_sync(0xffffffffu, inc, 31);
    unsigned ex = inc - s;
    unsigned ball = __ballot_sync(0xffffffffu, (int)ex <= rank);
    int sel = 31 - __clz(ball);
    int d = 0, r = rank;
    if (lane == sel) {
        r = rank - (int)ex;
        d = lane * chunk;
        for (int j = 0; j < chunk; j++) {
            unsigned c = hc[j];
            if (r < (int)c) { d = lane * chunk + j; break; }
            r -= (int)c;
        }
    }
    d = __shfl_sync(0xffffffffu, d, sel);
    r = __shfl_sync(0xffffffffu, r, sel);
    rank = r;
    return d;
}

// ---------------- zero histograms (wide grid, ~1us) ----------------
__global__ void k_zero() {
    int i = blockIdx.x * blockDim.x + threadIdx.x;
    int stride = gridDim.x * blockDim.x;
    unsigned* h = &g_qh[0][0][0];
    const int total = BATCH * 2 * NB;
    for (int j = i; j < total; j += stride) h[j] = 0u;
    if (i < BATCH) {
        g_below[i][0] = 0u;
        g_below[i][1] = 0u;
        g_fail[i] = 0;
    }
}

// ---------------- sampled bounds (one block per batch) ----------------
__global__ __launch_bounds__(1024) void k_bounds(const float* __restrict__ x) {
    __shared__ unsigned h[8192];
    __shared__ float red[64];
    __shared__ int sb[4];
    __shared__ float s_mn, s_scale;
    int b = blockIdx.x;
    const float* xb = x + (size_t)b * HW;
    int tid = threadIdx.x;

    float mn = __int_as_float(0x7f800000), mx = -mn;
    for (int i = tid; i < NSAMP; i += 1024) {
        float v = xb[sample_idx(i)];
        mn = fminf(mn, v); mx = fmaxf(mx, v);
    }
#pragma unroll
    for (int o = 16; o > 0; o >>= 1) {
        mn = fminf(mn, __shfl_down_sync(0xffffffffu, mn, o));
        mx = fmaxf(mx, __shfl_down_sync(0xffffffffu, mx, o));
    }
    int w = tid >> 5;
    if ((tid & 31) == 0) { red[w] = mn; red[32 + w] = mx; }
    __syncthreads();
    if (tid == 0) {
        float m0 = red[0], m1 = red[32];
        for (int i = 1; i < 32; i++) { m0 = fminf(m0, red[i]); m1 = fmaxf(m1, red[32 + i]); }
        s_mn = m0;
        float span = m1 - m0;
        s_scale = (span > 1e-20f) ? 8192.0f / span : -1.0f;
    }
    for (int i = tid; i < 8192; i += 1024) h[i] = 0u;
    __syncthreads();
    float smn = s_mn, sscale = s_scale;
    if (sscale < 0.f) {
        if (tid == 0) {
            g_fail[b] = 1;
            float inf = __int_as_float(0x7f800000);
            g_slo[b][0] = inf; g_shi[b][0] = inf;
            g_slo[b][1] = inf; g_shi[b][1] = inf;
        }
        return;
    }
    float bw8 = 1.0f / sscale;

    for (int i = tid; i < NSAMP; i += 1024) {
        float v = xb[sample_idx(i)];
        int bin = (int)((v - smn) * sscale);
        atomicAdd(&h[min(max(bin, 0), 8191)], 1u);
    }
    __syncthreads();
    if (w < 4) {
        int r = c_wrank[w];
        unsigned tot;
        int d = warp_walk_tot(h, 8192, r, tot);
        if ((tid & 31) == 0) sb[w] = d;
    }
    __syncthreads();
    if (tid == 0) {
        float inf = __int_as_float(0x7f800000);
        float l0 = smn + (float)(sb[0] - 1) * bw8;
        float h0 = smn + (float)(sb[1] + 2) * bw8;
        float l1 = smn + (float)(sb[2] - 1) * bw8;
        float h1 = smn + (float)(sb[3] + 2) * bw8;
        int merged = (l1 <= h0);
        if (merged) { h0 = h1; l1 = inf; h1 = inf; }
        g_merged[b] = merged;
        g_slo[b][0] = l0; g_shi[b][0] = h0;
        g_sinv[b][0] = (float)NB / (h0 - l0);
        g_sbw[b][0] = (h0 - l0) / (float)NB;
        g_slo[b][1] = l1; g_shi[b][1] = h1;
        if (!merged) {
            g_sinv[b][1] = (float)NB / (h1 - l1);
            g_sbw[b][1] = (h1 - l1) / (float)NB;
        } else {
            g_sinv[b][1] = 0.f; g_sbw[b][1] = 0.f;
        }
    }
}

// ---------------- one full scan: below-counts + bracketed value histogram ----------------
__global__ __launch_bounds__(256) void k_qhist(const float* __restrict__ x) {
    int b = blockIdx.y;
    float l0 = g_slo[b][0], h0 = g_shi[b][0], inv0 = g_sinv[b][0];
    float l1 = g_slo[b][1], h1 = g_shi[b][1], inv1 = g_sinv[b][1];
    unsigned* hist0 = g_qh[b][0];
    unsigned* hist1 = g_qh[b][1];
    unsigned below0 = 0, below1 = 0;

    const float4* xb = (const float4*)(x + (size_t)b * HW);
    const int nvec = HW / 4;
    for (int i = blockIdx.x * blockDim.x + threadIdx.x; i < nvec; i += gridDim.x * blockDim.x) {
        float4 v4 = xb[i];
        float vs[4] = {v4.x, v4.y, v4.z, v4.w};
#pragma unroll
        for (int e = 0; e < 4; e++) {
            float v = vs[e];
            below0 += (v < l0);
            below1 += (v < l1);
            if (v >= l0 && v < h0) {
                int bin = (int)((v - l0) * inv0);
                atomicAdd(&hist0[min(bin, NB - 1)], 1u);
            } else if (v >= l1 && v < h1) {
                int bin = (int)((v - l1) * inv1);
                atomicAdd(&hist1[min(bin, NB - 1)], 1u);
            }
        }
    }
#pragma unroll
    for (int o = 16; o > 0; o >>= 1) {
        below0 += __shfl_down_sync(0xffffffffu, below0, o);
        below1 += __shfl_down_sync(0xffffffffu, below1, o);
    }
    if ((threadIdx.x & 31) == 0) {
        atomicAdd(&g_below[b][0], below0);
        atomicAdd(&g_below[b][1], below1);
    }
}

// ---------------- finalize: block-parallel interpolating walk ----------------
#define QCHUNK (NB / 256)
__global__ __launch_bounds__(512) void k_qfinal() {
    int b = blockIdx.x;
    if (g_fail[b]) return;
    __shared__ unsigned sums[2][256];
    __shared__ float qres[2];
    __shared__ int sfail;
    int tid = threadIdx.x;
    int hh = tid >> 8;
    int t = tid & 255;
    if (tid == 0) sfail = 0;
    int merged = g_merged[b];
    int slot = (hh == 0) ? 0 : (merged ? 0 : 1);
    int K = (hh == 0) ? 20971 : 1027603;
    const unsigned* hist = g_qh[b][slot];

    unsigned s = 0;
#pragma unroll 8
    for (int j = 0; j < QCHUNK; j++) s += hist[t * QCHUNK + j];
    sums[hh][t] = s;
    __syncthreads();
    for (int o = 1; o < 256; o <<= 1) {
        unsigned v = (t >= o) ? sums[hh][t - o] : 0u;
        __syncthreads();
        sums[hh][t] += v;
        __syncthreads();
    }
    unsigned inc = sums[hh][t];
    unsigned ex = inc - s;
    unsigned total = sums[hh][255];
    int r = K - (int)g_below[b][slot];
    if (r < 0 || (unsigned)r >= total) {
        if (t == 0) sfail = 1;
    } else if ((int)ex <= r && r < (int)inc) {
        int rr = r - (int)ex;
        int d = t * QCHUNK;
        unsigned n = 0;
        for (int j = 0; j < QCHUNK; j++) {
            unsigned c = hist[t * QCHUNK + j];
            if (rr < (int)c) { d = t * QCHUNK + j; n = c; break; }
            rr -= (int)c;
        }
        qres[hh] = g_slo[b][slot] + ((float)d + ((float)rr + 1.0f) / (float)n) * g_sbw[b][slot];
    }
    __syncthreads();
    if (tid == 0) {
        if (sfail) g_fail[b] = 1;
        else {
            float lo = qres[0], hi = qres[1];
            g_lo[b] = lo;
            g_den[b] = hi - lo + EPSV;
        }
    }
}

// ---------------- rescue: full exact per-batch select (gated; normally no-op) ----------------
__global__ void k_rescue(const float* __restrict__ x) {
    int b = blockIdx.x;
    if (!g_fail[b]) return;
    __shared__ unsigned h[8192];
    __shared__ int sbin[4], sd2[4], srnk[4];
    const float* xb = x + (size_t)b * HW;

    for (int i = threadIdx.x; i < 8192; i += blockDim.x) h[i] = 0u;
    __syncthreads();
    for (int i = threadIdx.x; i < HW; i += blockDim.x)
        atomicAdd(&h[f2key(xb[i]) >> 19], 1u);
    __syncthreads();
    int w = threadIdx.x >> 5;
    if (w < 4) {
        int r = c_ranks[w];
        unsigned tot;
        int d = warp_walk_tot(h, 8192, r, tot);
        if ((threadIdx.x & 31) == 0) { sbin[w] = d; srnk[w] = r; }
    }
    __syncthreads();
    for (int t = 0; t < 4; t++) {
        for (int i = threadIdx.x; i < 2048; i += blockDim.x) h[i] = 0u;
        __syncthreads();
        unsigned tb = (unsigned)sbin[t];
        for (int i = threadIdx.x; i < HW; i += blockDim.x) {
            unsigned k = f2key(xb[i]);
            if ((k >> 19) == tb) atomicAdd(&h[(k >> 8) & 2047u], 1u);
        }
        __syncthreads();
        if (w == 0) {
            int r = srnk[t];
            unsigned tot;
            int d = warp_walk_tot(h, 2048, r, tot);
            if ((threadIdx.x & 31) == 0) { sd2[t] = d; srnk[t] = r; }
        }
        __syncthreads();
    }
    for (int t = 0; t < 4; t++) {
        for (int i = threadIdx.x; i < 256; i += blockDim.x) h[i] = 0u;
        __syncthreads();
        unsigned pre = ((unsigned)sbin[t] << 11) | (unsigned)sd2[t];
        for (int i = threadIdx.x; i < HW; i += blockDim.x) {
            unsigned k = f2key(xb[i]);
            if ((k >> 8) == pre) atomicAdd(&h[k & 255u], 1u);
        }
        __syncthreads();
        if (w == 0) {
            int r = srnk[t];
            unsigned tot;
            int d = warp_walk_tot(h, 256, r, tot);
            if ((threadIdx.x & 31) == 0)
                g_qval[b][t] = key2f(((unsigned)sbin[t] << 19) | ((unsigned)sd2[t] << 8) | (unsigned)d);
        }
        __syncthreads();
    }
    if (threadIdx.x == 0) {
        float q0 = g_qval[b][0], q1 = g_qval[b][1];
        float q2 = g_qval[b][2], q3 = g_qval[b][3];
        float lo = q0 + 0.5f * (q1 - q0);
        float hi = q2 + 0.5f * (q3 - q2);
        g_lo[b] = lo;
        g_den[b] = hi - lo + EPSV;
    }
}

// ---------------- fused: normalize + sobel + atan2 + dir-max + end map (R8 exact) ----------------
#define TS 64
#define HALO 6
#define SW (TS + 2 * HALO)   // 76
#define SPITCH (SW + 1)      // 77

__global__ __launch_bounds__(512) void k_fused(const float* __restrict__ x,
                                               float* __restrict__ emap,
                                               float* __restrict__ binsf,
                                               float* __restrict__ xnout) {
    __shared__ float tile[SW * SPITCH];
    int b = blockIdx.z;
    int bx = blockIdx.x * TS, by = blockIdx.y * TS;
    const float* xb = x + (size_t)b * HW;
    int tid = threadIdx.x;
    int l64 = tid & 63;
    int grp = tid >> 6;   // 0..7

    float lo = g_lo[b];
    float den = g_den[b];

    bool interior = (bx >= HALO) && (bx + TS + HALO <= W) && (by >= HALO) && (by + TS + HALO <= H);
    if (interior) {
        const float* src = xb + (size_t)(by - HALO) * W + (bx - HALO);
        for (int r = grp; r < SW; r += 8) {
            const float* row = src + r * W;
            float* trow = &tile[r * SPITCH];
            for (int c = l64; c < SW; c += 64)
                trow[c] = fminf(fmaxf((row[c] - lo) / den, 0.f), 1.f);
        }
    } else {
        for (int r = grp; r < SW; r += 8) {
            int gy = by + r - HALO;
            float* trow = &tile[r * SPITCH];
            for (int c = l64; c < SW; c += 64) {
                int gx = bx + c - HALO;
                float v = 0.f;
                if ((unsigned)gy < H && (unsigned)gx < W)
                    v = fminf(fmaxf((xb[gy * W + gx] - lo) / den, 0.f), 1.f);
                trow[c] = v;
            }
        }
    }
    __syncthreads();

#pragma unroll
    for (int k = 0; k < 8; k++) {
        int ly = grp + k * 8;
        int ty = ly + HALO, tx = l64 + HALO;
        const float* t0 = &tile[ty * SPITCH + tx];

        float a00 = t0[-SPITCH - 1], a01 = t0[-SPITCH], a02 = t0[-SPITCH + 1];
        float a10 = t0[-1], a12 = t0[1];
        float a20 = t0[SPITCH - 1], a21 = t0[SPITCH], a22 = t0[SPITCH + 1];
        float gxs = (a02 - a00) + 2.f * (a12 - a10) + (a22 - a20);
        float gys = (a20 - a00) + 2.f * (a21 - a01) + (a22 - a02);

        float ang = atan2f(gys, gxs);
        if (ang < 0.f) ang += TWO_PI_F;
        int bin = (int)floorf(ang / STEP_F);
        bin = min(max(bin, 0), 7);
        int b8 = (bin + 2) & 7;

        int dy = c_dy[b8], dx = c_dx[b8];
        int step = dy * SPITCH + dx;
        float f = 0.f, w = 0.f;
#pragma unroll
        for (int r = 1; r <= 6; r++) {
            f = fmaxf(f, t0[-step * r]);
            w = fmaxf(w, t0[ step * r]);
        }
        float mn = fminf(f, w), mx = fmaxf(f, w);
        float ratio = mn / (mx + EPSV);
        float x0 = t0[0];
        float em = fminf(fmaxf(x0 * (1.f - ratio), 0.f), 1.f);

        size_t o = (size_t)b * HW + (size_t)(by + ly) * W + (bx + l64);
        __stcs(&emap[o], em);
        if (binsf) __stcs(&binsf[o], (float)b8);
        if (xnout) __stcs(&xnout[o], x0);
    }
}

// ---------------- launch ----------------
extern "C" void kernel_launch(void* const* d_in, const int* in_sizes, int n_in,
                              void* d_out, int out_size) {
    const float* x = (const float*)d_in[0];
    float* out = (float*)d_out;
    const size_t N = (size_t)BATCH * HW;

    float* emap  = out;
    float* binsf = ((size_t)out_size >= 2 * N) ? out + N : nullptr;
    float* xnout = ((size_t)out_size >= 3 * N) ? out + 2 * N : nullptr;

    k_zero<<<256, 256>>>();
    k_bounds<<<BATCH, 1024>>>(x);
    k_qhist<<<dim3(64, BATCH), 256>>>(x);
    k_qfinal<<<BATCH, 512>>>();
    k_rescue<<<BATCH, 256>>>(x);

    dim3 gf(W / TS, H / TS, BATCH);
    k_fused<<<gf, 512>>>(x, emap, binsf, xnout);
}

// round 14
// speedup vs baseline: 1.3163x; 1.0341x over previous
#include <cuda_runtime.h>
#include <math.h>
#include <stdint.h>

#define BATCH 16
#define H 1024
#define W 1024
#define HW (H * W)
#define NB 16384
#define NSAMP 65536
#define TWO_PI_F 6.28318530717958647692f
#define STEP_F 0.78539816339744830962f
#define EPSV 1e-6f

__constant__ int c_ranks[4] = {20971, 20972, 1027603, 1027604};
__constant__ int c_wrank[4] = {968, 1653, 63883, 64567};

// ---------------- device scratch ----------------
__device__ unsigned g_qh[BATCH][2][NB];
__device__ unsigned g_below[BATCH][2];
__device__ float    g_slo[BATCH][2];
__device__ float    g_shi[BATCH][2];
__device__ float    g_sinv[BATCH][2];
__device__ float    g_sbw[BATCH][2];
__device__ int      g_merged[BATCH];
__device__ int      g_fail[BATCH];
__device__ float    g_lo[BATCH];
__device__ float    g_den[BATCH];
__device__ float    g_qval[BATCH][4];

__constant__ int c_dy[8] = {0, -1, -1, -1, 0, 1, 1, 1};
__constant__ int c_dx[8] = {1, 1, 0, -1, -1, -1, 0, 1};

__device__ __forceinline__ unsigned f2key(float f) {
    unsigned u = __float_as_uint(f);
    return (u & 0x80000000u) ? ~u : (u | 0x80000000u);
}
__device__ __forceinline__ float key2f(unsigned k) {
    unsigned u = (k & 0x80000000u) ? (k & 0x7fffffffu) : ~k;
    return __uint_as_float(u);
}
__device__ __forceinline__ int sample_idx(int i) {
    int chunk = i >> 6;
    int off = (chunk * 7919) & 960;
    return (chunk << 10) + off + (i & 63);
}

__device__ __forceinline__ int warp_walk_tot(const unsigned* hist, int nb, int& rank, unsigned& total) {
    int lane = threadIdx.x & 31;
    int chunk = nb / 32;
    const unsigned* hc = hist + lane * chunk;
    unsigned s = 0;
    for (int j = 0; j < chunk; j++) s += hc[j];
    unsigned inc = s;
#pragma unroll
    for (int o = 1; o < 32; o <<= 1) {
        unsigned v = __shfl_up_sync(0xffffffffu, inc, o);
        if (lane >= o) inc += v;
    }
    total = __shfl_sync(0xffffffffu, inc, 31);
    unsigned ex = inc - s;
    unsigned ball = __ballot_sync(0xffffffffu, (int)ex <= rank);
    int sel = 31 - __clz(ball);
    int d = 0, r = rank;
    if (lane == sel) {
        r = rank - (int)ex;
        d = lane * chunk;
        for (int j = 0; j < chunk; j++) {
            unsigned c = hc[j];
            if (r < (int)c) { d = lane * chunk + j; break; }
            r -= (int)c;
        }
    }
    d = __shfl_sync(0xffffffffu, d, sel);
    r = __shfl_sync(0xffffffffu, r, sel);
    rank = r;
    return d;
}

// ---------------- zero histograms (wide grid, ~1us) ----------------
__global__ void k_zero() {
    int i = blockIdx.x * blockDim.x + threadIdx.x;
    int stride = gridDim.x * blockDim.x;
    unsigned* h = &g_qh[0][0][0];
    const int total = BATCH * 2 * NB;
    for (int j = i; j < total; j += stride) h[j] = 0u;
    if (i < BATCH) {
        g_below[i][0] = 0u;
        g_below[i][1] = 0u;
        g_fail[i] = 0;
    }
}

// ---------------- sampled bounds (one block per batch) ----------------
__global__ __launch_bounds__(1024) void k_bounds(const float* __restrict__ x) {
    __shared__ unsigned h[8192];
    __shared__ float red[64];
    __shared__ int sb[4];
    __shared__ float s_mn, s_scale;
    int b = blockIdx.x;
    const float* xb = x + (size_t)b * HW;
    int tid = threadIdx.x;

    float mn = __int_as_float(0x7f800000), mx = -mn;
    for (int i = tid; i < NSAMP; i += 1024) {
        float v = xb[sample_idx(i)];
        mn = fminf(mn, v); mx = fmaxf(mx, v);
    }
#pragma unroll
    for (int o = 16; o > 0; o >>= 1) {
        mn = fminf(mn, __shfl_down_sync(0xffffffffu, mn, o));
        mx = fmaxf(mx, __shfl_down_sync(0xffffffffu, mx, o));
    }
    int w = tid >> 5;
    if ((tid & 31) == 0) { red[w] = mn; red[32 + w] = mx; }
    __syncthreads();
    if (tid == 0) {
        float m0 = red[0], m1 = red[32];
        for (int i = 1; i < 32; i++) { m0 = fminf(m0, red[i]); m1 = fmaxf(m1, red[32 + i]); }
        s_mn = m0;
        float span = m1 - m0;
        s_scale = (span > 1e-20f) ? 8192.0f / span : -1.0f;
    }
    for (int i = tid; i < 8192; i += 1024) h[i] = 0u;
    __syncthreads();
    float smn = s_mn, sscale = s_scale;
    if (sscale < 0.f) {
        if (tid == 0) {
            g_fail[b] = 1;
            float inf = __int_as_float(0x7f800000);
            g_slo[b][0] = inf; g_shi[b][0] = inf;
            g_slo[b][1] = inf; g_shi[b][1] = inf;
        }
        return;
    }
    float bw8 = 1.0f / sscale;

    for (int i = tid; i < NSAMP; i += 1024) {
        float v = xb[sample_idx(i)];
        int bin = (int)((v - smn) * sscale);
        atomicAdd(&h[min(max(bin, 0), 8191)], 1u);
    }
    __syncthreads();
    if (w < 4) {
        int r = c_wrank[w];
        unsigned tot;
        int d = warp_walk_tot(h, 8192, r, tot);
        if ((tid & 31) == 0) sb[w] = d;
    }
    __syncthreads();
    if (tid == 0) {
        float inf = __int_as_float(0x7f800000);
        float l0 = smn + (float)(sb[0] - 1) * bw8;
        float h0 = smn + (float)(sb[1] + 2) * bw8;
        float l1 = smn + (float)(sb[2] - 1) * bw8;
        float h1 = smn + (float)(sb[3] + 2) * bw8;
        int merged = (l1 <= h0);
        if (merged) { h0 = h1; l1 = inf; h1 = inf; }
        g_merged[b] = merged;
        g_slo[b][0] = l0; g_shi[b][0] = h0;
        g_sinv[b][0] = (float)NB / (h0 - l0);
        g_sbw[b][0] = (h0 - l0) / (float)NB;
        g_slo[b][1] = l1; g_shi[b][1] = h1;
        if (!merged) {
            g_sinv[b][1] = (float)NB / (h1 - l1);
            g_sbw[b][1] = (h1 - l1) / (float)NB;
        } else {
            g_sinv[b][1] = 0.f; g_sbw[b][1] = 0.f;
        }
    }
}

// ---------------- one full scan: below-counts + bracketed value histogram ----------------
__global__ __launch_bounds__(256) void k_qhist(const float* __restrict__ x) {
    int b = blockIdx.y;
    float l0 = g_slo[b][0], h0 = g_shi[b][0], inv0 = g_sinv[b][0];
    float l1 = g_slo[b][1], h1 = g_shi[b][1], inv1 = g_sinv[b][1];
    unsigned* hist0 = g_qh[b][0];
    unsigned* hist1 = g_qh[b][1];
    unsigned below0 = 0, below1 = 0;

    const float4* xb = (const float4*)(x + (size_t)b * HW);
    const int nvec = HW / 4;
    for (int i = blockIdx.x * blockDim.x + threadIdx.x; i < nvec; i += gridDim.x * blockDim.x) {
        float4 v4 = xb[i];
        float vs[4] = {v4.x, v4.y, v4.z, v4.w};
#pragma unroll
        for (int e = 0; e < 4; e++) {
            float v = vs[e];
            below0 += (v < l0);
            below1 += (v < l1);
            if (v >= l0 && v < h0) {
                int bin = (int)((v - l0) * inv0);
                atomicAdd(&hist0[min(bin, NB - 1)], 1u);
            } else if (v >= l1 && v < h1) {
                int bin = (int)((v - l1) * inv1);
                atomicAdd(&hist1[min(bin, NB - 1)], 1u);
            }
        }
    }
#pragma unroll
    for (int o = 16; o > 0; o >>= 1) {
        below0 += __shfl_down_sync(0xffffffffu, below0, o);
        below1 += __shfl_down_sync(0xffffffffu, below1, o);
    }
    if ((threadIdx.x & 31) == 0) {
        atomicAdd(&g_below[b][0], below0);
        atomicAdd(&g_below[b][1], below1);
    }
}

// ---------------- finalize: coalesced chunk sums + smem scan + tiny walk ----------------
#define QCHUNK 64              // bins per chunk
#define NCHUNK (NB / QCHUNK)   // 256 chunks per histogram
__global__ __launch_bounds__(512) void k_qfinal() {
    int b = blockIdx.x;
    if (g_fail[b]) return;
    __shared__ unsigned csum[2][NCHUNK];
    __shared__ float qres[2];
    __shared__ int sfail;
    int tid = threadIdx.x;
    int lane = tid & 31;
    int w = tid >> 5;          // 0..15
    if (tid == 0) sfail = 0;
    int merged = g_merged[b];
    const unsigned* hist_h[2] = { g_qh[b][0], g_qh[b][merged ? 0 : 1] };

    // phase 1: coalesced chunk sums. 512 chunks total (2 hists x 256), 32 per warp.
#pragma unroll
    for (int cc = 0; cc < 32; cc++) {
        int c = w * 32 + cc;          // 0..511
        int hh = c >> 8;
        int ch = c & 255;
        const unsigned* base = hist_h[hh] + ch * QCHUNK;
        unsigned v = base[lane] + base[32 + lane];   // two coalesced 128B loads
        unsigned s = __reduce_add_sync(0xffffffffu, v);
        if (lane == 0) csum[hh][ch] = s;
    }
    __syncthreads();

    // phase 2: Hillis-Steele scan over 256 chunk sums per quantile (in smem)
    int hh = tid >> 8;         // 0..1
    int t = tid & 255;
    unsigned s = csum[hh][t];
    unsigned inc = s;
    for (int o = 1; o < 256; o <<= 1) {
        unsigned v = (t >= o) ? csum[hh][t - o] : 0u;
        __syncthreads();
        csum[hh][t] = inc = inc + v;
        __syncthreads();
    }
    unsigned ex = inc - s;
    unsigned total = csum[hh][255];
    int slot = (hh == 0) ? 0 : (merged ? 0 : 1);
    int K = (hh == 0) ? 20971 : 1027603;
    int r = K - (int)g_below[b][slot];
    if (r < 0 || (unsigned)r >= total) {
        if (t == 0) sfail = 1;
    } else if ((int)ex <= r && r < (int)inc) {
        // this thread's chunk contains the rank: walk 64 bins via 16 uint4 loads
        int rr = r - (int)ex;
        const uint4* hc4 = (const uint4*)(hist_h[hh] + t * QCHUNK);
        int d = t * QCHUNK;
        unsigned n = 0;
#pragma unroll
        for (int j4 = 0; j4 < 16; j4++) {
            uint4 q = hc4[j4];
            unsigned e4[4] = {q.x, q.y, q.z, q.w};
#pragma unroll
            for (int e = 0; e < 4; e++) {
                unsigned c = e4[e];
                if (n == 0) {
                    if (rr < (int)c) { d = t * QCHUNK + j4 * 4 + e; n = c; }
                    else rr -= (int)c;
                }
            }
        }
        qres[hh] = g_slo[b][slot] + ((float)d + ((float)rr + 1.0f) / (float)n) * g_sbw[b][slot];
    }
    __syncthreads();
    if (tid == 0) {
        if (sfail) g_fail[b] = 1;
        else {
            float lo = qres[0], hi = qres[1];
            g_lo[b] = lo;
            g_den[b] = hi - lo + EPSV;
        }
    }
}

// ---------------- rescue: full exact per-batch select (gated; normally no-op) ----------------
__global__ void k_rescue(const float* __restrict__ x) {
    int b = blockIdx.x;
    if (!g_fail[b]) return;
    __shared__ unsigned h[8192];
    __shared__ int sbin[4], sd2[4], srnk[4];
    const float* xb = x + (size_t)b * HW;

    for (int i = threadIdx.x; i < 8192; i += blockDim.x) h[i] = 0u;
    __syncthreads();
    for (int i = threadIdx.x; i < HW; i += blockDim.x)
        atomicAdd(&h[f2key(xb[i]) >> 19], 1u);
    __syncthreads();
    int w = threadIdx.x >> 5;
    if (w < 4) {
        int r = c_ranks[w];
        unsigned tot;
        int d = warp_walk_tot(h, 8192, r, tot);
        if ((threadIdx.x & 31) == 0) { sbin[w] = d; srnk[w] = r; }
    }
    __syncthreads();
    for (int t = 0; t < 4; t++) {
        for (int i = threadIdx.x; i < 2048; i += blockDim.x) h[i] = 0u;
        __syncthreads();
        unsigned tb = (unsigned)sbin[t];
        for (int i = threadIdx.x; i < HW; i += blockDim.x) {
            unsigned k = f2key(xb[i]);
            if ((k >> 19) == tb) atomicAdd(&h[(k >> 8) & 2047u], 1u);
        }
        __syncthreads();
        if (w == 0) {
            int r = srnk[t];
            unsigned tot;
            int d = warp_walk_tot(h, 2048, r, tot);
            if ((threadIdx.x & 31) == 0) { sd2[t] = d; srnk[t] = r; }
        }
        __syncthreads();
    }
    for (int t = 0; t < 4; t++) {
        for (int i = threadIdx.x; i < 256; i += blockDim.x) h[i] = 0u;
        __syncthreads();
        unsigned pre = ((unsigned)sbin[t] << 11) | (unsigned)sd2[t];
        for (int i = threadIdx.x; i < HW; i += blockDim.x) {
            unsigned k = f2key(xb[i]);
            if ((k >> 8) == pre) atomicAdd(&h[k & 255u], 1u);
        }
        __syncthreads();
        if (w == 0) {
            int r = srnk[t];
            unsigned tot;
            int d = warp_walk_tot(h, 256, r, tot);
            if ((threadIdx.x & 31) == 0)
                g_qval[b][t] = key2f(((unsigned)sbin[t] << 19) | ((unsigned)sd2[t] << 8) | (unsigned)d);
        }
        __syncthreads();
    }
    if (threadIdx.x == 0) {
        float q0 = g_qval[b][0], q1 = g_qval[b][1];
        float q2 = g_qval[b][2], q3 = g_qval[b][3];
        float lo = q0 + 0.5f * (q1 - q0);
        float hi = q2 + 0.5f * (q3 - q2);
        g_lo[b] = lo;
        g_den[b] = hi - lo + EPSV;
    }
}

// ---------------- fused: normalize + sobel + atan2 + dir-max + end map (R8 exact) ----------------
#define TS 64
#define HALO 6
#define SW (TS + 2 * HALO)   // 76
#define SPITCH (SW + 1)      // 77

__global__ __launch_bounds__(512) void k_fused(const float* __restrict__ x,
                                               float* __restrict__ emap,
                                               float* __restrict__ binsf,
                                               float* __restrict__ xnout) {
    __shared__ float tile[SW * SPITCH];
    int b = blockIdx.z;
    int bx = blockIdx.x * TS, by = blockIdx.y * TS;
    const float* xb = x + (size_t)b * HW;
    int tid = threadIdx.x;
    int l64 = tid & 63;
    int grp = tid >> 6;   // 0..7

    float lo = g_lo[b];
    float den = g_den[b];

    bool interior = (bx >= HALO) && (bx + TS + HALO <= W) && (by >= HALO) && (by + TS + HALO <= H);
    if (interior) {
        const float* src = xb + (size_t)(by - HALO) * W + (bx - HALO);
        for (int r = grp; r < SW; r += 8) {
            const float* row = src + r * W;
            float* trow = &tile[r * SPITCH];
            for (int c = l64; c < SW; c += 64)
                trow[c] = fminf(fmaxf((row[c] - lo) / den, 0.f), 1.f);
        }
    } else {
        for (int r = grp; r < SW; r += 8) {
            int gy = by + r - HALO;
            float* trow = &tile[r * SPITCH];
            for (int c = l64; c < SW; c += 64) {
                int gx = bx + c - HALO;
                float v = 0.f;
                if ((unsigned)gy < H && (unsigned)gx < W)
                    v = fminf(fmaxf((xb[gy * W + gx] - lo) / den, 0.f), 1.f);
                trow[c] = v;
            }
        }
    }
    __syncthreads();

#pragma unroll
    for (int k = 0; k < 8; k++) {
        int ly = grp + k * 8;
        int ty = ly + HALO, tx = l64 + HALO;
        const float* t0 = &tile[ty * SPITCH + tx];

        float a00 = t0[-SPITCH - 1], a01 = t0[-SPITCH], a02 = t0[-SPITCH + 1];
        float a10 = t0[-1], a12 = t0[1];
        float a20 = t0[SPITCH - 1], a21 = t0[SPITCH], a22 = t0[SPITCH + 1];
        float gxs = (a02 - a00) + 2.f * (a12 - a10) + (a22 - a20);
        float gys = (a20 - a00) + 2.f * (a21 - a01) + (a22 - a02);

        float ang = atan2f(gys, gxs);
        if (ang < 0.f) ang += TWO_PI_F;
        int bin = (int)floorf(ang / STEP_F);
        bin = min(max(bin, 0), 7);
        int b8 = (bin + 2) & 7;

        int dy = c_dy[b8], dx = c_dx[b8];
        int step = dy * SPITCH + dx;
        float f = 0.f, w = 0.f;
#pragma unroll
        for (int r = 1; r <= 6; r++) {
            f = fmaxf(f, t0[-step * r]);
            w = fmaxf(w, t0[ step * r]);
        }
        float mn = fminf(f, w), mx = fmaxf(f, w);
        float ratio = mn / (mx + EPSV);
        float x0 = t0[0];
        float em = fminf(fmaxf(x0 * (1.f - ratio), 0.f), 1.f);

        size_t o = (size_t)b * HW + (size_t)(by + ly) * W + (bx + l64);
        __stcs(&emap[o], em);
        if (binsf) __stcs(&binsf[o], (float)b8);
        if (xnout) __stcs(&xnout[o], x0);
    }
}

// ---------------- launch ----------------
extern "C" void kernel_launch(void* const* d_in, const int* in_sizes, int n_in,
                              void* d_out, int out_size) {
    const float* x = (const float*)d_in[0];
    float* out = (float*)d_out;
    const size_t N = (size_t)BATCH * HW;

    float* emap  = out;
    float* binsf = ((size_t)out_size >= 2 * N) ? out + N : nullptr;
    float* xnout = ((size_t)out_size >= 3 * N) ? out + 2 * N : nullptr;

    k_zero<<<256, 256>>>();
    k_bounds<<<BATCH, 1024>>>(x);
    k_qhist<<<dim3(64, BATCH), 256>>>(x);
    k_qfinal<<<BATCH, 512>>>();
    k_rescue<<<BATCH, 256>>>(x);

    dim3 gf(W / TS, H / TS, BATCH);
    k_fused<<<gf, 512>>>(x, emap, binsf, xnout);
}

// round 15
// speedup vs baseline: 1.3437x; 1.0208x over previous
#include <cuda_runtime.h>
#include <math.h>
#include <stdint.h>

#define BATCH 16
#define H 1024
#define W 1024
#define HW (H * W)
#define NB 16384
#define NSAMP 65536
#define TWO_PI_F 6.28318530717958647692f
#define STEP_F 0.78539816339744830962f
#define EPSV 1e-6f

#define QCHUNK 64              // bins per chunk
#define NCHUNK (NB / QCHUNK)   // 256 chunks per histogram

__constant__ int c_ranks[4] = {20971, 20972, 1027603, 1027604};
__constant__ int c_wrank[4] = {968, 1653, 63883, 64567};

// ---------------- device scratch ----------------
__device__ unsigned g_qh[BATCH][2][NB];
__device__ unsigned g_csum[BATCH][2][NCHUNK];
__device__ unsigned g_below[BATCH][2];
__device__ float    g_slo[BATCH][2];
__device__ float    g_shi[BATCH][2];
__device__ float    g_sinv[BATCH][2];
__device__ float    g_sbw[BATCH][2];
__device__ int      g_merged[BATCH];
__device__ int      g_fail[BATCH];
__device__ float    g_lo[BATCH];
__device__ float    g_den[BATCH];
__device__ float    g_qval[BATCH][4];

__constant__ int c_dy[8] = {0, -1, -1, -1, 0, 1, 1, 1};
__constant__ int c_dx[8] = {1, 1, 0, -1, -1, -1, 0, 1};

__device__ __forceinline__ unsigned f2key(float f) {
    unsigned u = __float_as_uint(f);
    return (u & 0x80000000u) ? ~u : (u | 0x80000000u);
}
__device__ __forceinline__ float key2f(unsigned k) {
    unsigned u = (k & 0x80000000u) ? (k & 0x7fffffffu) : ~k;
    return __uint_as_float(u);
}
__device__ __forceinline__ int sample_idx(int i) {
    int chunk = i >> 6;
    int off = (chunk * 7919) & 960;
    return (chunk << 10) + off + (i & 63);
}

__device__ __forceinline__ int warp_walk_tot(const unsigned* hist, int nb, int& rank, unsigned& total) {
    int lane = threadIdx.x & 31;
    int chunk = nb / 32;
    const unsigned* hc = hist + lane * chunk;
    unsigned s = 0;
    for (int j = 0; j < chunk; j++) s += hc[j];
    unsigned inc = s;
#pragma unroll
    for (int o = 1; o < 32; o <<= 1) {
        unsigned v = __shfl_up_sync(0xffffffffu, inc, o);
        if (lane >= o) inc += v;
    }
    total = __shfl_sync(0xffffffffu, inc, 31);
    unsigned ex = inc - s;
    unsigned ball = __ballot_sync(0xffffffffu, (int)ex <= rank);
    int sel = 31 - __clz(ball);
    int d = 0, r = rank;
    if (lane == sel) {
        r = rank - (int)ex;
        d = lane * chunk;
        for (int j = 0; j < chunk; j++) {
            unsigned c = hc[j];
            if (r < (int)c) { d = lane * chunk + j; break; }
            r -= (int)c;
        }
    }
    d = __shfl_sync(0xffffffffu, d, sel);
    r = __shfl_sync(0xffffffffu, r, sel);
    rank = r;
    return d;
}

// ---------------- zero histograms (wide grid, ~1us) ----------------
__global__ void k_zero() {
    int i = blockIdx.x * blockDim.x + threadIdx.x;
    int stride = gridDim.x * blockDim.x;
    unsigned* h = &g_qh[0][0][0];
    const int total = BATCH * 2 * NB;
    for (int j = i; j < total; j += stride) h[j] = 0u;
    if (i < BATCH) {
        g_below[i][0] = 0u;
        g_below[i][1] = 0u;
        g_fail[i] = 0;
    }
}

// ---------------- sampled bounds (one block per batch) ----------------
__global__ __launch_bounds__(1024) void k_bounds(const float* __restrict__ x) {
    __shared__ unsigned h[8192];
    __shared__ float red[64];
    __shared__ int sb[4];
    __shared__ float s_mn, s_scale;
    int b = blockIdx.x;
    const float* xb = x + (size_t)b * HW;
    int tid = threadIdx.x;

    float mn = __int_as_float(0x7f800000), mx = -mn;
    for (int i = tid; i < NSAMP; i += 1024) {
        float v = xb[sample_idx(i)];
        mn = fminf(mn, v); mx = fmaxf(mx, v);
    }
#pragma unroll
    for (int o = 16; o > 0; o >>= 1) {
        mn = fminf(mn, __shfl_down_sync(0xffffffffu, mn, o));
        mx = fmaxf(mx, __shfl_down_sync(0xffffffffu, mx, o));
    }
    int w = tid >> 5;
    if ((tid & 31) == 0) { red[w] = mn; red[32 + w] = mx; }
    __syncthreads();
    if (tid == 0) {
        float m0 = red[0], m1 = red[32];
        for (int i = 1; i < 32; i++) { m0 = fminf(m0, red[i]); m1 = fmaxf(m1, red[32 + i]); }
        s_mn = m0;
        float span = m1 - m0;
        s_scale = (span > 1e-20f) ? 8192.0f / span : -1.0f;
    }
    for (int i = tid; i < 8192; i += 1024) h[i] = 0u;
    __syncthreads();
    float smn = s_mn, sscale = s_scale;
    if (sscale < 0.f) {
        if (tid == 0) {
            g_fail[b] = 1;
            float inf = __int_as_float(0x7f800000);
            g_slo[b][0] = inf; g_shi[b][0] = inf;
            g_slo[b][1] = inf; g_shi[b][1] = inf;
        }
        return;
    }
    float bw8 = 1.0f / sscale;

    for (int i = tid; i < NSAMP; i += 1024) {
        float v = xb[sample_idx(i)];
        int bin = (int)((v - smn) * sscale);
        atomicAdd(&h[min(max(bin, 0), 8191)], 1u);
    }
    __syncthreads();
    if (w < 4) {
        int r = c_wrank[w];
        unsigned tot;
        int d = warp_walk_tot(h, 8192, r, tot);
        if ((tid & 31) == 0) sb[w] = d;
    }
    __syncthreads();
    if (tid == 0) {
        float inf = __int_as_float(0x7f800000);
        float l0 = smn + (float)(sb[0] - 1) * bw8;
        float h0 = smn + (float)(sb[1] + 2) * bw8;
        float l1 = smn + (float)(sb[2] - 1) * bw8;
        float h1 = smn + (float)(sb[3] + 2) * bw8;
        int merged = (l1 <= h0);
        if (merged) { h0 = h1; l1 = inf; h1 = inf; }
        g_merged[b] = merged;
        g_slo[b][0] = l0; g_shi[b][0] = h0;
        g_sinv[b][0] = (float)NB / (h0 - l0);
        g_sbw[b][0] = (h0 - l0) / (float)NB;
        g_slo[b][1] = l1; g_shi[b][1] = h1;
        if (!merged) {
            g_sinv[b][1] = (float)NB / (h1 - l1);
            g_sbw[b][1] = (h1 - l1) / (float)NB;
        } else {
            g_sinv[b][1] = 0.f; g_sbw[b][1] = 0.f;
        }
    }
}

// ---------------- one full scan: below-counts + bracketed value histogram ----------------
__global__ __launch_bounds__(256) void k_qhist(const float* __restrict__ x) {
    int b = blockIdx.y;
    float l0 = g_slo[b][0], h0 = g_shi[b][0], inv0 = g_sinv[b][0];
    float l1 = g_slo[b][1], h1 = g_shi[b][1], inv1 = g_sinv[b][1];
    unsigned* hist0 = g_qh[b][0];
    unsigned* hist1 = g_qh[b][1];
    unsigned below0 = 0, below1 = 0;

    const float4* xb = (const float4*)(x + (size_t)b * HW);
    const int nvec = HW / 4;
    for (int i = blockIdx.x * blockDim.x + threadIdx.x; i < nvec; i += gridDim.x * blockDim.x) {
        float4 v4 = xb[i];
        float vs[4] = {v4.x, v4.y, v4.z, v4.w};
#pragma unroll
        for (int e = 0; e < 4; e++) {
            float v = vs[e];
            below0 += (v < l0);
            below1 += (v < l1);
            if (v >= l0 && v < h0) {
                int bin = (int)((v - l0) * inv0);
                atomicAdd(&hist0[min(bin, NB - 1)], 1u);
            } else if (v >= l1 && v < h1) {
                int bin = (int)((v - l1) * inv1);
                atomicAdd(&hist1[min(bin, NB - 1)], 1u);
            }
        }
    }
#pragma unroll
    for (int o = 16; o > 0; o >>= 1) {
        below0 += __shfl_down_sync(0xffffffffu, below0, o);
        below1 += __shfl_down_sync(0xffffffffu, below1, o);
    }
    if ((threadIdx.x & 31) == 0) {
        atomicAdd(&g_below[b][0], below0);
        atomicAdd(&g_below[b][1], below1);
    }
}

// ---------------- chunk sums: wide-grid warp-cooperative (full-chip, ~2us) ----------------
__global__ __launch_bounds__(256) void k_qsum() {
    int lane = threadIdx.x & 31;
    int gwarp = (blockIdx.x * blockDim.x + threadIdx.x) >> 5;
    int nwarps = (gridDim.x * blockDim.x) >> 5;
    const int total_chunks = BATCH * 2 * NCHUNK;   // 8192
    const unsigned* hbase = &g_qh[0][0][0];
    unsigned* cbase = &g_csum[0][0][0];
    for (int c = gwarp; c < total_chunks; c += nwarps) {
        const unsigned* base = hbase + c * QCHUNK;
        unsigned v = base[lane] + base[32 + lane];
        unsigned s = __reduce_add_sync(0xffffffffu, v);
        if (lane == 0) cbase[c] = s;
    }
}

// ---------------- finalize: smem scan over chunk sums + tiny walk ----------------
__global__ __launch_bounds__(512) void k_qfinal() {
    int b = blockIdx.x;
    if (g_fail[b]) return;
    __shared__ unsigned csum[2][NCHUNK];
    __shared__ float qres[2];
    __shared__ int sfail;
    int tid = threadIdx.x;
    if (tid == 0) sfail = 0;
    int merged = g_merged[b];

    int hh = tid >> 8;         // 0..1
    int t = tid & 255;
    int slot = (hh == 0) ? 0 : (merged ? 0 : 1);
    const unsigned* hist = g_qh[b][slot];

    // coalesced load of precomputed chunk sums
    unsigned s = g_csum[b][slot][t];
    csum[hh][t] = s;
    __syncthreads();
    unsigned inc = s;
    for (int o = 1; o < 256; o <<= 1) {
        unsigned v = (t >= o) ? csum[hh][t - o] : 0u;
        __syncthreads();
        csum[hh][t] = inc = inc + v;
        __syncthreads();
    }
    unsigned ex = inc - s;
    unsigned total = csum[hh][255];
    int K = (hh == 0) ? 20971 : 1027603;
    int r = K - (int)g_below[b][slot];
    if (r < 0 || (unsigned)r >= total) {
        if (t == 0) sfail = 1;
    } else if ((int)ex <= r && r < (int)inc) {
        int rr = r - (int)ex;
        const uint4* hc4 = (const uint4*)(hist + t * QCHUNK);
        int d = t * QCHUNK;
        unsigned n = 0;
#pragma unroll
        for (int j4 = 0; j4 < 16; j4++) {
            uint4 q = hc4[j4];
            unsigned e4[4] = {q.x, q.y, q.z, q.w};
#pragma unroll
            for (int e = 0; e < 4; e++) {
                unsigned c = e4[e];
                if (n == 0) {
                    if (rr < (int)c) { d = t * QCHUNK + j4 * 4 + e; n = c; }
                    else rr -= (int)c;
                }
            }
        }
        qres[hh] = g_slo[b][slot] + ((float)d + ((float)rr + 1.0f) / (float)n) * g_sbw[b][slot];
    }
    __syncthreads();
    if (tid == 0) {
        if (sfail) g_fail[b] = 1;
        else {
            float lo = qres[0], hi = qres[1];
            g_lo[b] = lo;
            g_den[b] = hi - lo + EPSV;
        }
    }
}

// ---------------- rescue: full exact per-batch select (gated; normally no-op) ----------------
__global__ void k_rescue(const float* __restrict__ x) {
    int b = blockIdx.x;
    if (!g_fail[b]) return;
    __shared__ unsigned h[8192];
    __shared__ int sbin[4], sd2[4], srnk[4];
    const float* xb = x + (size_t)b * HW;

    for (int i = threadIdx.x; i < 8192; i += blockDim.x) h[i] = 0u;
    __syncthreads();
    for (int i = threadIdx.x; i < HW; i += blockDim.x)
        atomicAdd(&h[f2key(xb[i]) >> 19], 1u);
    __syncthreads();
    int w = threadIdx.x >> 5;
    if (w < 4) {
        int r = c_ranks[w];
        unsigned tot;
        int d = warp_walk_tot(h, 8192, r, tot);
        if ((threadIdx.x & 31) == 0) { sbin[w] = d; srnk[w] = r; }
    }
    __syncthreads();
    for (int t = 0; t < 4; t++) {
        for (int i = threadIdx.x; i < 2048; i += blockDim.x) h[i] = 0u;
        __syncthreads();
        unsigned tb = (unsigned)sbin[t];
        for (int i = threadIdx.x; i < HW; i += blockDim.x) {
            unsigned k = f2key(xb[i]);
            if ((k >> 19) == tb) atomicAdd(&h[(k >> 8) & 2047u], 1u);
        }
        __syncthreads();
        if (w == 0) {
            int r = srnk[t];
            unsigned tot;
            int d = warp_walk_tot(h, 2048, r, tot);
            if ((threadIdx.x & 31) == 0) { sd2[t] = d; srnk[t] = r; }
        }
        __syncthreads();
    }
    for (int t = 0; t < 4; t++) {
        for (int i = threadIdx.x; i < 256; i += blockDim.x) h[i] = 0u;
        __syncthreads();
        unsigned pre = ((unsigned)sbin[t] << 11) | (unsigned)sd2[t];
        for (int i = threadIdx.x; i < HW; i += blockDim.x) {
            unsigned k = f2key(xb[i]);
            if ((k >> 8) == pre) atomicAdd(&h[k & 255u], 1u);
        }
        __syncthreads();
        if (w == 0) {
            int r = srnk[t];
            unsigned tot;
            int d = warp_walk_tot(h, 256, r, tot);
            if ((threadIdx.x & 31) == 0)
                g_qval[b][t] = key2f(((unsigned)sbin[t] << 19) | ((unsigned)sd2[t] << 8) | (unsigned)d);
        }
        __syncthreads();
    }
    if (threadIdx.x == 0) {
        float q0 = g_qval[b][0], q1 = g_qval[b][1];
        float q2 = g_qval[b][2], q3 = g_qval[b][3];
        float lo = q0 + 0.5f * (q1 - q0);
        float hi = q2 + 0.5f * (q3 - q2);
        g_lo[b] = lo;
        g_den[b] = hi - lo + EPSV;
    }
}

// ---------------- fused: normalize + sobel + atan2 + dir-max + end map (R8 exact) ----------------
#define TS 64
#define HALO 6
#define SW (TS + 2 * HALO)   // 76
#define SPITCH (SW + 1)      // 77

__global__ __launch_bounds__(512) void k_fused(const float* __restrict__ x,
                                               float* __restrict__ emap,
                                               float* __restrict__ binsf,
                                               float* __restrict__ xnout) {
    __shared__ float tile[SW * SPITCH];
    int b = blockIdx.z;
    int bx = blockIdx.x * TS, by = blockIdx.y * TS;
    const float* xb = x + (size_t)b * HW;
    int tid = threadIdx.x;
    int l64 = tid & 63;
    int grp = tid >> 6;   // 0..7

    float lo = g_lo[b];
    float den = g_den[b];

    bool interior = (bx >= HALO) && (bx + TS + HALO <= W) && (by >= HALO) && (by + TS + HALO <= H);
    if (interior) {
        const float* src = xb + (size_t)(by - HALO) * W + (bx - HALO);
        for (int r = grp; r < SW; r += 8) {
            const float* row = src + r * W;
            float* trow = &tile[r * SPITCH];
            for (int c = l64; c < SW; c += 64)
                trow[c] = fminf(fmaxf((row[c] - lo) / den, 0.f), 1.f);
        }
    } else {
        for (int r = grp; r < SW; r += 8) {
            int gy = by + r - HALO;
            float* trow = &tile[r * SPITCH];
            for (int c = l64; c < SW; c += 64) {
                int gx = bx + c - HALO;
                float v = 0.f;
                if ((unsigned)gy < H && (unsigned)gx < W)
                    v = fminf(fmaxf((xb[gy * W + gx] - lo) / den, 0.f), 1.f);
                trow[c] = v;
            }
        }
    }
    __syncthreads();

#pragma unroll
    for (int k = 0; k < 8; k++) {
        int ly = grp + k * 8;
        int ty = ly + HALO, tx = l64 + HALO;
        const float* t0 = &tile[ty * SPITCH + tx];

        float a00 = t0[-SPITCH - 1], a01 = t0[-SPITCH], a02 = t0[-SPITCH + 1];
        float a10 = t0[-1], a12 = t0[1];
        float a20 = t0[SPITCH - 1], a21 = t0[SPITCH], a22 = t0[SPITCH + 1];
        float gxs = (a02 - a00) + 2.f * (a12 - a10) + (a22 - a20);
        float gys = (a20 - a00) + 2.f * (a21 - a01) + (a22 - a02);

        float ang = atan2f(gys, gxs);
        if (ang < 0.f) ang += TWO_PI_F;
        int bin = (int)floorf(ang / STEP_F);
        bin = min(max(bin, 0), 7);
        int b8 = (bin + 2) & 7;

        int dy = c_dy[b8], dx = c_dx[b8];
        int step = dy * SPITCH + dx;
        float f = 0.f, w = 0.f;
#pragma unroll
        for (int r = 1; r <= 6; r++) {
            f = fmaxf(f, t0[-step * r]);
            w = fmaxf(w, t0[ step * r]);
        }
        float mn = fminf(f, w), mx = fmaxf(f, w);
        float ratio = mn / (mx + EPSV);
        float x0 = t0[0];
        float em = fminf(fmaxf(x0 * (1.f - ratio), 0.f), 1.f);

        size_t o = (size_t)b * HW + (size_t)(by + ly) * W + (bx + l64);
        __stcs(&emap[o], em);
        if (binsf) __stcs(&binsf[o], (float)b8);
        if (xnout) __stcs(&xnout[o], x0);
    }
}

// ---------------- launch ----------------
extern "C" void kernel_launch(void* const* d_in, const int* in_sizes, int n_in,
                              void* d_out, int out_size) {
    const float* x = (const float*)d_in[0];
    float* out = (float*)d_out;
    const size_t N = (size_t)BATCH * HW;

    float* emap  = out;
    float* binsf = ((size_t)out_size >= 2 * N) ? out + N : nullptr;
    float* xnout = ((size_t)out_size >= 3 * N) ? out + 2 * N : nullptr;

    k_zero<<<256, 256>>>();
    k_bounds<<<BATCH, 1024>>>(x);
    k_qhist<<<dim3(64, BATCH), 256>>>(x);
    k_qsum<<<128, 256>>>();
    k_qfinal<<<BATCH, 512>>>();
    k_rescue<<<BATCH, 256>>>(x);

    dim3 gf(W / TS, H / TS, BATCH);
    k_fused<<<gf, 512>>>(x, emap, binsf, xnout);
}

// round 16
// speedup vs baseline: 1.4368x; 1.0693x over previous
#include <cuda_runtime.h>
#include <math.h>
#include <stdint.h>

#define BATCH 16
#define H 1024
#define W 1024
#define HW (H * W)
#define NB 16384
#define NSAMP 65536
#define TWO_PI_F 6.28318530717958647692f
#define STEP_F 0.78539816339744830962f
#define EPSV 1e-6f

#define QCHUNK 64              // bins per chunk
#define NCHUNK (NB / QCHUNK)   // 256 chunks per histogram

__constant__ int c_ranks[4] = {20971, 20972, 1027603, 1027604};
__constant__ int c_wrank[4] = {968, 1653, 63883, 64567};

// ---------------- device scratch ----------------
__device__ unsigned g_qh[BATCH][2][NB];
__device__ unsigned g_csum[BATCH][2][NCHUNK];
__device__ unsigned g_below[BATCH][2];
__device__ float    g_slo[BATCH][2];
__device__ float    g_shi[BATCH][2];
__device__ float    g_sinv[BATCH][2];
__device__ float    g_sbw[BATCH][2];
__device__ int      g_merged[BATCH];
__device__ int      g_fail[BATCH];
__device__ float    g_lo[BATCH];
__device__ float    g_den[BATCH];
__device__ float    g_qval[BATCH][4];

__constant__ int c_dy[8] = {0, -1, -1, -1, 0, 1, 1, 1};
__constant__ int c_dx[8] = {1, 1, 0, -1, -1, -1, 0, 1};

__device__ __forceinline__ unsigned f2key(float f) {
    unsigned u = __float_as_uint(f);
    return (u & 0x80000000u) ? ~u : (u | 0x80000000u);
}
__device__ __forceinline__ float key2f(unsigned k) {
    unsigned u = (k & 0x80000000u) ? (k & 0x7fffffffu) : ~k;
    return __uint_as_float(u);
}
__device__ __forceinline__ int sample_idx(int i) {
    int chunk = i >> 6;
    int off = (chunk * 7919) & 960;
    return (chunk << 10) + off + (i & 63);
}

__device__ __forceinline__ int warp_walk_tot(const unsigned* hist, int nb, int& rank, unsigned& total) {
    int lane = threadIdx.x & 31;
    int chunk = nb / 32;
    const unsigned* hc = hist + lane * chunk;
    unsigned s = 0;
    for (int j = 0; j < chunk; j++) s += hc[j];
    unsigned inc = s;
#pragma unroll
    for (int o = 1; o < 32; o <<= 1) {
        unsigned v = __shfl_up_sync(0xffffffffu, inc, o);
        if (lane >= o) inc += v;
    }
    total = __shfl_sync(0xffffffffu, inc, 31);
    unsigned ex = inc - s;
    unsigned ball = __ballot_sync(0xffffffffu, (int)ex <= rank);
    int sel = 31 - __clz(ball);
    int d = 0, r = rank;
    if (lane == sel) {
        r = rank - (int)ex;
        d = lane * chunk;
        for (int j = 0; j < chunk; j++) {
            unsigned c = hc[j];
            if (r < (int)c) { d = lane * chunk + j; break; }
            r -= (int)c;
        }
    }
    d = __shfl_sync(0xffffffffu, d, sel);
    r = __shfl_sync(0xffffffffu, r, sel);
    rank = r;
    return d;
}

// ---------------- zero histograms (wide grid, ~1us) ----------------
__global__ void k_zero() {
    int i = blockIdx.x * blockDim.x + threadIdx.x;
    int stride = gridDim.x * blockDim.x;
    unsigned* h = &g_qh[0][0][0];
    const int total = BATCH * 2 * NB;
    for (int j = i; j < total; j += stride) h[j] = 0u;
    if (i < BATCH) {
        g_below[i][0] = 0u;
        g_below[i][1] = 0u;
        g_fail[i] = 0;
    }
}

// ---------------- sampled bounds (one block per batch) ----------------
__global__ __launch_bounds__(1024) void k_bounds(const float* __restrict__ x) {
    __shared__ unsigned h[8192];
    __shared__ float red[64];
    __shared__ int sb[4];
    __shared__ float s_mn, s_scale;
    int b = blockIdx.x;
    const float* xb = x + (size_t)b * HW;
    int tid = threadIdx.x;

    float mn = __int_as_float(0x7f800000), mx = -mn;
    for (int i = tid; i < NSAMP; i += 1024) {
        float v = xb[sample_idx(i)];
        mn = fminf(mn, v); mx = fmaxf(mx, v);
    }
#pragma unroll
    for (int o = 16; o > 0; o >>= 1) {
        mn = fminf(mn, __shfl_down_sync(0xffffffffu, mn, o));
        mx = fmaxf(mx, __shfl_down_sync(0xffffffffu, mx, o));
    }
    int w = tid >> 5;
    if ((tid & 31) == 0) { red[w] = mn; red[32 + w] = mx; }
    __syncthreads();
    if (tid == 0) {
        float m0 = red[0], m1 = red[32];
        for (int i = 1; i < 32; i++) { m0 = fminf(m0, red[i]); m1 = fmaxf(m1, red[32 + i]); }
        s_mn = m0;
        float span = m1 - m0;
        s_scale = (span > 1e-20f) ? 8192.0f / span : -1.0f;
    }
    for (int i = tid; i < 8192; i += 1024) h[i] = 0u;
    __syncthreads();
    float smn = s_mn, sscale = s_scale;
    if (sscale < 0.f) {
        if (tid == 0) {
            g_fail[b] = 1;
            float inf = __int_as_float(0x7f800000);
            g_slo[b][0] = inf; g_shi[b][0] = inf;
            g_slo[b][1] = inf; g_shi[b][1] = inf;
        }
        return;
    }
    float bw8 = 1.0f / sscale;

    for (int i = tid; i < NSAMP; i += 1024) {
        float v = xb[sample_idx(i)];
        int bin = (int)((v - smn) * sscale);
        atomicAdd(&h[min(max(bin, 0), 8191)], 1u);
    }
    __syncthreads();
    if (w < 4) {
        int r = c_wrank[w];
        unsigned tot;
        int d = warp_walk_tot(h, 8192, r, tot);
        if ((tid & 31) == 0) sb[w] = d;
    }
    __syncthreads();
    if (tid == 0) {
        float inf = __int_as_float(0x7f800000);
        float l0 = smn + (float)(sb[0] - 1) * bw8;
        float h0 = smn + (float)(sb[1] + 2) * bw8;
        float l1 = smn + (float)(sb[2] - 1) * bw8;
        float h1 = smn + (float)(sb[3] + 2) * bw8;
        int merged = (l1 <= h0);
        if (merged) { h0 = h1; l1 = inf; h1 = inf; }
        g_merged[b] = merged;
        g_slo[b][0] = l0; g_shi[b][0] = h0;
        g_sinv[b][0] = (float)NB / (h0 - l0);
        g_sbw[b][0] = (h0 - l0) / (float)NB;
        g_slo[b][1] = l1; g_shi[b][1] = h1;
        if (!merged) {
            g_sinv[b][1] = (float)NB / (h1 - l1);
            g_sbw[b][1] = (h1 - l1) / (float)NB;
        } else {
            g_sinv[b][1] = 0.f; g_sbw[b][1] = 0.f;
        }
    }
}

// ---------------- one full scan: below-counts + bracketed value histogram ----------------
__global__ __launch_bounds__(256) void k_qhist(const float* __restrict__ x) {
    int b = blockIdx.y;
    float l0 = g_slo[b][0], h0 = g_shi[b][0], inv0 = g_sinv[b][0];
    float l1 = g_slo[b][1], h1 = g_shi[b][1], inv1 = g_sinv[b][1];
    unsigned* hist0 = g_qh[b][0];
    unsigned* hist1 = g_qh[b][1];
    unsigned below0 = 0, below1 = 0;

    const float4* xb = (const float4*)(x + (size_t)b * HW);
    const int nvec = HW / 4;
    for (int i = blockIdx.x * blockDim.x + threadIdx.x; i < nvec; i += gridDim.x * blockDim.x) {
        float4 v4 = xb[i];
        float vs[4] = {v4.x, v4.y, v4.z, v4.w};
#pragma unroll
        for (int e = 0; e < 4; e++) {
            float v = vs[e];
            below0 += (v < l0);
            below1 += (v < l1);
            if (v >= l0 && v < h0) {
                int bin = (int)((v - l0) * inv0);
                atomicAdd(&hist0[min(bin, NB - 1)], 1u);
            } else if (v >= l1 && v < h1) {
                int bin = (int)((v - l1) * inv1);
                atomicAdd(&hist1[min(bin, NB - 1)], 1u);
            }
        }
    }
#pragma unroll
    for (int o = 16; o > 0; o >>= 1) {
        below0 += __shfl_down_sync(0xffffffffu, below0, o);
        below1 += __shfl_down_sync(0xffffffffu, below1, o);
    }
    if ((threadIdx.x & 31) == 0) {
        atomicAdd(&g_below[b][0], below0);
        atomicAdd(&g_below[b][1], below1);
    }
}

// ---------------- chunk sums: wide-grid warp-cooperative (full-chip) ----------------
__global__ __launch_bounds__(256) void k_qsum() {
    int lane = threadIdx.x & 31;
    int gwarp = (blockIdx.x * blockDim.x + threadIdx.x) >> 5;
    int nwarps = (gridDim.x * blockDim.x) >> 5;
    const int total_chunks = BATCH * 2 * NCHUNK;   // 8192
    const unsigned* hbase = &g_qh[0][0][0];
    unsigned* cbase = &g_csum[0][0][0];
    for (int c = gwarp; c < total_chunks; c += nwarps) {
        const unsigned* base = hbase + c * QCHUNK;
        unsigned v = base[lane] + base[32 + lane];
        unsigned s = __reduce_add_sync(0xffffffffu, v);
        if (lane == 0) cbase[c] = s;
    }
}

// ---------------- finalize: smem scan over chunk sums + tiny walk ----------------
__global__ __launch_bounds__(512) void k_qfinal() {
    int b = blockIdx.x;
    if (g_fail[b]) return;
    __shared__ unsigned csum[2][NCHUNK];
    __shared__ float qres[2];
    __shared__ int sfail;
    int tid = threadIdx.x;
    if (tid == 0) sfail = 0;
    int merged = g_merged[b];

    int hh = tid >> 8;         // 0..1
    int t = tid & 255;
    int slot = (hh == 0) ? 0 : (merged ? 0 : 1);
    const unsigned* hist = g_qh[b][slot];

    unsigned s = g_csum[b][slot][t];
    csum[hh][t] = s;
    __syncthreads();
    unsigned inc = s;
    for (int o = 1; o < 256; o <<= 1) {
        unsigned v = (t >= o) ? csum[hh][t - o] : 0u;
        __syncthreads();
        csum[hh][t] = inc = inc + v;
        __syncthreads();
    }
    unsigned ex = inc - s;
    unsigned total = csum[hh][255];
    int K = (hh == 0) ? 20971 : 1027603;
    int r = K - (int)g_below[b][slot];
    if (r < 0 || (unsigned)r >= total) {
        if (t == 0) sfail = 1;
    } else if ((int)ex <= r && r < (int)inc) {
        int rr = r - (int)ex;
        const uint4* hc4 = (const uint4*)(hist + t * QCHUNK);
        int d = t * QCHUNK;
        unsigned n = 0;
#pragma unroll
        for (int j4 = 0; j4 < 16; j4++) {
            uint4 q = hc4[j4];
            unsigned e4[4] = {q.x, q.y, q.z, q.w};
#pragma unroll
            for (int e = 0; e < 4; e++) {
                unsigned c = e4[e];
                if (n == 0) {
                    if (rr < (int)c) { d = t * QCHUNK + j4 * 4 + e; n = c; }
                    else rr -= (int)c;
                }
            }
        }
        qres[hh] = g_slo[b][slot] + ((float)d + ((float)rr + 1.0f) / (float)n) * g_sbw[b][slot];
    }
    __syncthreads();
    if (tid == 0) {
        if (sfail) g_fail[b] = 1;
        else {
            float lo = qres[0], hi = qres[1];
            g_lo[b] = lo;
            g_den[b] = hi - lo + EPSV;
        }
    }
}

// ---------------- rescue: full exact per-batch select (gated; normally no-op) ----------------
__global__ void k_rescue(const float* __restrict__ x) {
    int b = blockIdx.x;
    if (!g_fail[b]) return;
    __shared__ unsigned h[8192];
    __shared__ int sbin[4], sd2[4], srnk[4];
    const float* xb = x + (size_t)b * HW;

    for (int i = threadIdx.x; i < 8192; i += blockDim.x) h[i] = 0u;
    __syncthreads();
    for (int i = threadIdx.x; i < HW; i += blockDim.x)
        atomicAdd(&h[f2key(xb[i]) >> 19], 1u);
    __syncthreads();
    int w = threadIdx.x >> 5;
    if (w < 4) {
        int r = c_ranks[w];
        unsigned tot;
        int d = warp_walk_tot(h, 8192, r, tot);
        if ((threadIdx.x & 31) == 0) { sbin[w] = d; srnk[w] = r; }
    }
    __syncthreads();
    for (int t = 0; t < 4; t++) {
        for (int i = threadIdx.x; i < 2048; i += blockDim.x) h[i] = 0u;
        __syncthreads();
        unsigned tb = (unsigned)sbin[t];
        for (int i = threadIdx.x; i < HW; i += blockDim.x) {
            unsigned k = f2key(xb[i]);
            if ((k >> 19) == tb) atomicAdd(&h[(k >> 8) & 2047u], 1u);
        }
        __syncthreads();
        if (w == 0) {
            int r = srnk[t];
            unsigned tot;
            int d = warp_walk_tot(h, 2048, r, tot);
            if ((threadIdx.x & 31) == 0) { sd2[t] = d; srnk[t] = r; }
        }
        __syncthreads();
    }
    for (int t = 0; t < 4; t++) {
        for (int i = threadIdx.x; i < 256; i += blockDim.x) h[i] = 0u;
        __syncthreads();
        unsigned pre = ((unsigned)sbin[t] << 11) | (unsigned)sd2[t];
        for (int i = threadIdx.x; i < HW; i += blockDim.x) {
            unsigned k = f2key(xb[i]);
            if ((k >> 8) == pre) atomicAdd(&h[k & 255u], 1u);
        }
        __syncthreads();
        if (w == 0) {
            int r = srnk[t];
            unsigned tot;
            int d = warp_walk_tot(h, 256, r, tot);
            if ((threadIdx.x & 31) == 0)
                g_qval[b][t] = key2f(((unsigned)sbin[t] << 19) | ((unsigned)sd2[t] << 8) | (unsigned)d);
        }
        __syncthreads();
    }
    if (threadIdx.x == 0) {
        float q0 = g_qval[b][0], q1 = g_qval[b][1];
        float q2 = g_qval[b][2], q3 = g_qval[b][3];
        float lo = q0 + 0.5f * (q1 - q0);
        float hi = q2 + 0.5f * (q3 - q2);
        g_lo[b] = lo;
        g_den[b] = hi - lo + EPSV;
    }
}

// ---------------- fused: normalize + sobel + octant + dir-max + end map ----------------
#define TS 64
#define HALO 6
#define SW (TS + 2 * HALO)   // 76
#define SPITCH (SW + 1)      // 77

__global__ __launch_bounds__(512) void k_fused(const float* __restrict__ x,
                                               float* __restrict__ emap,
                                               float* __restrict__ binsf,
                                               float* __restrict__ xnout) {
    __shared__ float tile[SW * SPITCH];
    int b = blockIdx.z;
    int bx = blockIdx.x * TS, by = blockIdx.y * TS;
    const float* xb = x + (size_t)b * HW;
    int tid = threadIdx.x;
    int l64 = tid & 63;
    int grp = tid >> 6;   // 0..7

    float lo = g_lo[b];
    float den = g_den[b];

    bool interior = (bx >= HALO) && (bx + TS + HALO <= W) && (by >= HALO) && (by + TS + HALO <= H);
    if (interior) {
        const float* src = xb + (size_t)(by - HALO) * W + (bx - HALO);
        for (int r = grp; r < SW; r += 8) {
            const float* row = src + r * W;
            float* trow = &tile[r * SPITCH];
            for (int c = l64; c < SW; c += 64)
                trow[c] = fminf(fmaxf((row[c] - lo) / den, 0.f), 1.f);
        }
    } else {
        for (int r = grp; r < SW; r += 8) {
            int gy = by + r - HALO;
            float* trow = &tile[r * SPITCH];
            for (int c = l64; c < SW; c += 64) {
                int gx = bx + c - HALO;
                float v = 0.f;
                if ((unsigned)gy < H && (unsigned)gx < W)
                    v = fminf(fmaxf((xb[gy * W + gx] - lo) / den, 0.f), 1.f);
                trow[c] = v;
            }
        }
    }
    __syncthreads();

#pragma unroll
    for (int k = 0; k < 8; k++) {
        int ly = grp + k * 8;
        int ty = ly + HALO, tx = l64 + HALO;
        const float* t0 = &tile[ty * SPITCH + tx];

        float a00 = t0[-SPITCH - 1], a01 = t0[-SPITCH], a02 = t0[-SPITCH + 1];
        float a10 = t0[-1], a12 = t0[1];
        float a20 = t0[SPITCH - 1], a21 = t0[SPITCH], a22 = t0[SPITCH + 1];
        float gxs = (a02 - a00) + 2.f * (a12 - a10) + (a22 - a20);
        float gys = (a20 - a00) + 2.f * (a21 - a01) + (a22 - a02);

        // branchless exact octant of atan2(gys,gxs) mod 2pi in pi/4 bins
        // (ties at k*pi/4 boundaries and +/-0 cases match atan2f rounding)
        int bin = (gxs > 0.f && gys >= 0.f) ? ((gys < gxs) ? 0 : 1)
                : (gys > 0.f)               ? ((-gxs < gys) ? 2 : 3)
                : (gxs < 0.f)               ? ((-gys < -gxs) ? 4 : 5)
                : (gys < 0.f)               ? ((gxs < -gys) ? 6 : 7)
                : 0;
        int b8 = (bin + 2) & 7;

        int dy = c_dy[b8], dx = c_dx[b8];
        int step = dy * SPITCH + dx;
        float f = 0.f, w = 0.f;
#pragma unroll
        for (int r = 1; r <= 6; r++) {
            f = fmaxf(f, t0[-step * r]);
            w = fmaxf(w, t0[ step * r]);
        }
        float mn = fminf(f, w), mx = fmaxf(f, w);
        float ratio = mn / (mx + EPSV);
        float x0 = t0[0];
        float em = fminf(fmaxf(x0 * (1.f - ratio), 0.f), 1.f);

        size_t o = (size_t)b * HW + (size_t)(by + ly) * W + (bx + l64);
        __stcs(&emap[o], em);
        if (binsf) __stcs(&binsf[o], (float)b8);
        if (xnout) __stcs(&xnout[o], x0);
    }
}

// ---------------- launch ----------------
extern "C" void kernel_launch(void* const* d_in, const int* in_sizes, int n_in,
                              void* d_out, int out_size) {
    const float* x = (const float*)d_in[0];
    float* out = (float*)d_out;
    const size_t N = (size_t)BATCH * HW;

    float* emap  = out;
    float* binsf = ((size_t)out_size >= 2 * N) ? out + N : nullptr;
    float* xnout = ((size_t)out_size >= 3 * N) ? out + 2 * N : nullptr;

    k_zero<<<256, 256>>>();
    k_bounds<<<BATCH, 1024>>>(x);
    k_qhist<<<dim3(64, BATCH), 256>>>(x);
    k_qsum<<<512, 256>>>();
    k_qfinal<<<BATCH, 512>>>();
    k_rescue<<<BATCH, 256>>>(x);

    dim3 gf(W / TS, H / TS, BATCH);
    k_fused<<<gf, 512>>>(x, emap, binsf, xnout);
}

// round 17
// speedup vs baseline: 1.5000x; 1.0440x over previous
#include <cuda_runtime.h>
#include <math.h>
#include <stdint.h>

#define BATCH 16
#define H 1024
#define W 1024
#define HW (H * W)
#define NB 16384
#define NSAMP 65536
#define TWO_PI_F 6.28318530717958647692f
#define STEP_F 0.78539816339744830962f
#define EPSV 1e-6f

#define QCHUNK 64              // bins per chunk
#define NCHUNK (NB / QCHUNK)   // 256 chunks per histogram

__constant__ int c_ranks[4] = {20971, 20972, 1027603, 1027604};
__constant__ int c_wrank[4] = {968, 1653, 63883, 64567};

// ---------------- device scratch ----------------
__device__ unsigned g_qh[BATCH][2][NB];
__device__ unsigned g_csum[BATCH][2][NCHUNK];
__device__ unsigned g_below[BATCH][2];
__device__ float    g_slo[BATCH][2];
__device__ float    g_shi[BATCH][2];
__device__ float    g_sinv[BATCH][2];
__device__ float    g_sbw[BATCH][2];
__device__ int      g_merged[BATCH];
__device__ int      g_fail[BATCH];
__device__ float    g_lo[BATCH];
__device__ float    g_invden[BATCH];
__device__ float    g_qval[BATCH][4];

__constant__ int c_dy[8] = {0, -1, -1, -1, 0, 1, 1, 1};
__constant__ int c_dx[8] = {1, 1, 0, -1, -1, -1, 0, 1};

__device__ __forceinline__ unsigned f2key(float f) {
    unsigned u = __float_as_uint(f);
    return (u & 0x80000000u) ? ~u : (u | 0x80000000u);
}
__device__ __forceinline__ float key2f(unsigned k) {
    unsigned u = (k & 0x80000000u) ? (k & 0x7fffffffu) : ~k;
    return __uint_as_float(u);
}
__device__ __forceinline__ int sample_idx(int i) {
    int chunk = i >> 6;
    int off = (chunk * 7919) & 960;
    return (chunk << 10) + off + (i & 63);
}

__device__ __forceinline__ int warp_walk_tot(const unsigned* hist, int nb, int& rank, unsigned& total) {
    int lane = threadIdx.x & 31;
    int chunk = nb / 32;
    const unsigned* hc = hist + lane * chunk;
    unsigned s = 0;
    for (int j = 0; j < chunk; j++) s += hc[j];
    unsigned inc = s;
#pragma unroll
    for (int o = 1; o < 32; o <<= 1) {
        unsigned v = __shfl_up_sync(0xffffffffu, inc, o);
        if (lane >= o) inc += v;
    }
    total = __shfl_sync(0xffffffffu, inc, 31);
    unsigned ex = inc - s;
    unsigned ball = __ballot_sync(0xffffffffu, (int)ex <= rank);
    int sel = 31 - __clz(ball);
    int d = 0, r = rank;
    if (lane == sel) {
        r = rank - (int)ex;
        d = lane * chunk;
        for (int j = 0; j < chunk; j++) {
            unsigned c = hc[j];
            if (r < (int)c) { d = lane * chunk + j; break; }
            r -= (int)c;
        }
    }
    d = __shfl_sync(0xffffffffu, d, sel);
    r = __shfl_sync(0xffffffffu, r, sel);
    rank = r;
    return d;
}

// ---------------- zero histograms (wide grid, ~1us) ----------------
__global__ void k_zero() {
    int i = blockIdx.x * blockDim.x + threadIdx.x;
    int stride = gridDim.x * blockDim.x;
    unsigned* h = &g_qh[0][0][0];
    const int total = BATCH * 2 * NB;
    for (int j = i; j < total; j += stride) h[j] = 0u;
    if (i < BATCH) {
        g_below[i][0] = 0u;
        g_below[i][1] = 0u;
        g_fail[i] = 0;
    }
}

// ---------------- sampled bounds (one block per batch) ----------------
__global__ __launch_bounds__(1024) void k_bounds(const float* __restrict__ x) {
    __shared__ unsigned h[8192];
    __shared__ float red[64];
    __shared__ int sb[4];
    __shared__ float s_mn, s_scale;
    int b = blockIdx.x;
    const float* xb = x + (size_t)b * HW;
    int tid = threadIdx.x;

    float mn = __int_as_float(0x7f800000), mx = -mn;
    for (int i = tid; i < NSAMP; i += 1024) {
        float v = xb[sample_idx(i)];
        mn = fminf(mn, v); mx = fmaxf(mx, v);
    }
#pragma unroll
    for (int o = 16; o > 0; o >>= 1) {
        mn = fminf(mn, __shfl_down_sync(0xffffffffu, mn, o));
        mx = fmaxf(mx, __shfl_down_sync(0xffffffffu, mx, o));
    }
    int w = tid >> 5;
    if ((tid & 31) == 0) { red[w] = mn; red[32 + w] = mx; }
    __syncthreads();
    if (tid == 0) {
        float m0 = red[0], m1 = red[32];
        for (int i = 1; i < 32; i++) { m0 = fminf(m0, red[i]); m1 = fmaxf(m1, red[32 + i]); }
        s_mn = m0;
        float span = m1 - m0;
        s_scale = (span > 1e-20f) ? 8192.0f / span : -1.0f;
    }
    for (int i = tid; i < 8192; i += 1024) h[i] = 0u;
    __syncthreads();
    float smn = s_mn, sscale = s_scale;
    if (sscale < 0.f) {
        if (tid == 0) {
            g_fail[b] = 1;
            float inf = __int_as_float(0x7f800000);
            g_slo[b][0] = inf; g_shi[b][0] = inf;
            g_slo[b][1] = inf; g_shi[b][1] = inf;
        }
        return;
    }
    float bw8 = 1.0f / sscale;

    for (int i = tid; i < NSAMP; i += 1024) {
        float v = xb[sample_idx(i)];
        int bin = (int)((v - smn) * sscale);
        atomicAdd(&h[min(max(bin, 0), 8191)], 1u);
    }
    __syncthreads();
    if (w < 4) {
        int r = c_wrank[w];
        unsigned tot;
        int d = warp_walk_tot(h, 8192, r, tot);
        if ((tid & 31) == 0) sb[w] = d;
    }
    __syncthreads();
    if (tid == 0) {
        float inf = __int_as_float(0x7f800000);
        float l0 = smn + (float)(sb[0] - 1) * bw8;
        float h0 = smn + (float)(sb[1] + 2) * bw8;
        float l1 = smn + (float)(sb[2] - 1) * bw8;
        float h1 = smn + (float)(sb[3] + 2) * bw8;
        int merged = (l1 <= h0);
        if (merged) { h0 = h1; l1 = inf; h1 = inf; }
        g_merged[b] = merged;
        g_slo[b][0] = l0; g_shi[b][0] = h0;
        g_sinv[b][0] = (float)NB / (h0 - l0);
        g_sbw[b][0] = (h0 - l0) / (float)NB;
        g_slo[b][1] = l1; g_shi[b][1] = h1;
        if (!merged) {
            g_sinv[b][1] = (float)NB / (h1 - l1);
            g_sbw[b][1] = (h1 - l1) / (float)NB;
        } else {
            g_sinv[b][1] = 0.f; g_sbw[b][1] = 0.f;
        }
    }
}

// ---------------- one full scan: below-counts + bracketed value histogram ----------------
__global__ __launch_bounds__(256) void k_qhist(const float* __restrict__ x) {
    int b = blockIdx.y;
    float l0 = g_slo[b][0], h0 = g_shi[b][0], inv0 = g_sinv[b][0];
    float l1 = g_slo[b][1], h1 = g_shi[b][1], inv1 = g_sinv[b][1];
    unsigned* hist0 = g_qh[b][0];
    unsigned* hist1 = g_qh[b][1];
    unsigned below0 = 0, below1 = 0;

    const float4* xb = (const float4*)(x + (size_t)b * HW);
    const int nvec = HW / 4;
    for (int i = blockIdx.x * blockDim.x + threadIdx.x; i < nvec; i += gridDim.x * blockDim.x) {
        float4 v4 = xb[i];
        float vs[4] = {v4.x, v4.y, v4.z, v4.w};
#pragma unroll
        for (int e = 0; e < 4; e++) {
            float v = vs[e];
            below0 += (v < l0);
            below1 += (v < l1);
            if (v >= l0 && v < h0) {
                int bin = (int)((v - l0) * inv0);
                atomicAdd(&hist0[min(bin, NB - 1)], 1u);
            } else if (v >= l1 && v < h1) {
                int bin = (int)((v - l1) * inv1);
                atomicAdd(&hist1[min(bin, NB - 1)], 1u);
            }
        }
    }
#pragma unroll
    for (int o = 16; o > 0; o >>= 1) {
        below0 += __shfl_down_sync(0xffffffffu, below0, o);
        below1 += __shfl_down_sync(0xffffffffu, below1, o);
    }
    if ((threadIdx.x & 31) == 0) {
        atomicAdd(&g_below[b][0], below0);
        atomicAdd(&g_below[b][1], below1);
    }
}

// ---------------- chunk sums: wide-grid warp-cooperative (full-chip) ----------------
__global__ __launch_bounds__(256) void k_qsum() {
    int lane = threadIdx.x & 31;
    int gwarp = (blockIdx.x * blockDim.x + threadIdx.x) >> 5;
    int nwarps = (gridDim.x * blockDim.x) >> 5;
    const int total_chunks = BATCH * 2 * NCHUNK;   // 8192
    const unsigned* hbase = &g_qh[0][0][0];
    unsigned* cbase = &g_csum[0][0][0];
    for (int c = gwarp; c < total_chunks; c += nwarps) {
        const unsigned* base = hbase + c * QCHUNK;
        unsigned v = base[lane] + base[32 + lane];
        unsigned s = __reduce_add_sync(0xffffffffu, v);
        if (lane == 0) cbase[c] = s;
    }
}

// ---------------- finalize: smem scan over chunk sums + tiny walk ----------------
__global__ __launch_bounds__(512) void k_qfinal() {
    int b = blockIdx.x;
    if (g_fail[b]) return;
    __shared__ unsigned csum[2][NCHUNK];
    __shared__ float qres[2];
    __shared__ int sfail;
    int tid = threadIdx.x;
    if (tid == 0) sfail = 0;
    int merged = g_merged[b];

    int hh = tid >> 8;         // 0..1
    int t = tid & 255;
    int slot = (hh == 0) ? 0 : (merged ? 0 : 1);
    const unsigned* hist = g_qh[b][slot];

    unsigned s = g_csum[b][slot][t];
    csum[hh][t] = s;
    __syncthreads();
    unsigned inc = s;
    for (int o = 1; o < 256; o <<= 1) {
        unsigned v = (t >= o) ? csum[hh][t - o] : 0u;
        __syncthreads();
        csum[hh][t] = inc = inc + v;
        __syncthreads();
    }
    unsigned ex = inc - s;
    unsigned total = csum[hh][255];
    int K = (hh == 0) ? 20971 : 1027603;
    int r = K - (int)g_below[b][slot];
    if (r < 0 || (unsigned)r >= total) {
        if (t == 0) sfail = 1;
    } else if ((int)ex <= r && r < (int)inc) {
        int rr = r - (int)ex;
        const uint4* hc4 = (const uint4*)(hist + t * QCHUNK);
        int d = t * QCHUNK;
        unsigned n = 0;
#pragma unroll
        for (int j4 = 0; j4 < 16; j4++) {
            uint4 q = hc4[j4];
            unsigned e4[4] = {q.x, q.y, q.z, q.w};
#pragma unroll
            for (int e = 0; e < 4; e++) {
                unsigned c = e4[e];
                if (n == 0) {
                    if (rr < (int)c) { d = t * QCHUNK + j4 * 4 + e; n = c; }
                    else rr -= (int)c;
                }
            }
        }
        qres[hh] = g_slo[b][slot] + ((float)d + ((float)rr + 1.0f) / (float)n) * g_sbw[b][slot];
    }
    __syncthreads();
    if (tid == 0) {
        if (sfail) g_fail[b] = 1;
        else {
            float lo = qres[0], hi = qres[1];
            g_lo[b] = lo;
            g_invden[b] = 1.0f / (hi - lo + EPSV);
        }
    }
}

// ---------------- rescue: full exact per-batch select (gated; normally no-op) ----------------
__global__ void k_rescue(const float* __restrict__ x) {
    int b = blockIdx.x;
    if (!g_fail[b]) return;
    __shared__ unsigned h[8192];
    __shared__ int sbin[4], sd2[4], srnk[4];
    const float* xb = x + (size_t)b * HW;

    for (int i = threadIdx.x; i < 8192; i += blockDim.x) h[i] = 0u;
    __syncthreads();
    for (int i = threadIdx.x; i < HW; i += blockDim.x)
        atomicAdd(&h[f2key(xb[i]) >> 19], 1u);
    __syncthreads();
    int w = threadIdx.x >> 5;
    if (w < 4) {
        int r = c_ranks[w];
        unsigned tot;
        int d = warp_walk_tot(h, 8192, r, tot);
        if ((threadIdx.x & 31) == 0) { sbin[w] = d; srnk[w] = r; }
    }
    __syncthreads();
    for (int t = 0; t < 4; t++) {
        for (int i = threadIdx.x; i < 2048; i += blockDim.x) h[i] = 0u;
        __syncthreads();
        unsigned tb = (unsigned)sbin[t];
        for (int i = threadIdx.x; i < HW; i += blockDim.x) {
            unsigned k = f2key(xb[i]);
            if ((k >> 19) == tb) atomicAdd(&h[(k >> 8) & 2047u], 1u);
        }
        __syncthreads();
        if (w == 0) {
            int r = srnk[t];
            unsigned tot;
            int d = warp_walk_tot(h, 2048, r, tot);
            if ((threadIdx.x & 31) == 0) { sd2[t] = d; srnk[t] = r; }
        }
        __syncthreads();
    }
    for (int t = 0; t < 4; t++) {
        for (int i = threadIdx.x; i < 256; i += blockDim.x) h[i] = 0u;
        __syncthreads();
        unsigned pre = ((unsigned)sbin[t] << 11) | (unsigned)sd2[t];
        for (int i = threadIdx.x; i < HW; i += blockDim.x) {
            unsigned k = f2key(xb[i]);
            if ((k >> 8) == pre) atomicAdd(&h[k & 255u], 1u);
        }
        __syncthreads();
        if (w == 0) {
            int r = srnk[t];
            unsigned tot;
            int d = warp_walk_tot(h, 256, r, tot);
            if ((threadIdx.x & 31) == 0)
                g_qval[b][t] = key2f(((unsigned)sbin[t] << 19) | ((unsigned)sd2[t] << 8) | (unsigned)d);
        }
        __syncthreads();
    }
    if (threadIdx.x == 0) {
        float q0 = g_qval[b][0], q1 = g_qval[b][1];
        float q2 = g_qval[b][2], q3 = g_qval[b][3];
        float lo = q0 + 0.5f * (q1 - q0);
        float hi = q2 + 0.5f * (q3 - q2);
        g_lo[b] = lo;
        g_invden[b] = 1.0f / (hi - lo + EPSV);
    }
}

// ---------------- fused: normalize + sobel + octant + dir-max + end map ----------------
#define TS 64
#define HALO 6
#define SW (TS + 2 * HALO)   // 76
#define SPITCH (SW + 1)      // 77

__global__ __launch_bounds__(512) void k_fused(const float* __restrict__ x,
                                               float* __restrict__ emap,
                                               float* __restrict__ binsf,
                                               float* __restrict__ xnout) {
    __shared__ float tile[SW * SPITCH];
    int b = blockIdx.z;
    int bx = blockIdx.x * TS, by = blockIdx.y * TS;
    const float* xb = x + (size_t)b * HW;
    int tid = threadIdx.x;
    int l64 = tid & 63;
    int grp = tid >> 6;   // 0..7

    float lo = g_lo[b];
    float invden = g_invden[b];

    bool interior = (bx >= HALO) && (bx + TS + HALO <= W) && (by >= HALO) && (by + TS + HALO <= H);
    if (interior) {
        const float* src = xb + (size_t)(by - HALO) * W + (bx - HALO);
        for (int r = grp; r < SW; r += 8) {
            const float* row = src + r * W;
            float* trow = &tile[r * SPITCH];
            for (int c = l64; c < SW; c += 64)
                trow[c] = fminf(fmaxf((row[c] - lo) * invden, 0.f), 1.f);
        }
    } else {
        for (int r = grp; r < SW; r += 8) {
            int gy = by + r - HALO;
            float* trow = &tile[r * SPITCH];
            for (int c = l64; c < SW; c += 64) {
                int gx = bx + c - HALO;
                float v = 0.f;
                if ((unsigned)gy < H && (unsigned)gx < W)
                    v = fminf(fmaxf((xb[gy * W + gx] - lo) * invden, 0.f), 1.f);
                trow[c] = v;
            }
        }
    }
    __syncthreads();

#pragma unroll
    for (int k = 0; k < 8; k++) {
        int ly = grp + k * 8;
        int ty = ly + HALO, tx = l64 + HALO;
        const float* t0 = &tile[ty * SPITCH + tx];

        float a00 = t0[-SPITCH - 1], a01 = t0[-SPITCH], a02 = t0[-SPITCH + 1];
        float a10 = t0[-1], a12 = t0[1];
        float a20 = t0[SPITCH - 1], a21 = t0[SPITCH], a22 = t0[SPITCH + 1];
        float gxs = (a02 - a00) + 2.f * (a12 - a10) + (a22 - a20);
        float gys = (a20 - a00) + 2.f * (a21 - a01) + (a22 - a02);

        // branchless exact octant of atan2(gys,gxs) mod 2pi in pi/4 bins
        int bin = (gxs > 0.f && gys >= 0.f) ? ((gys < gxs) ? 0 : 1)
                : (gys > 0.f)               ? ((-gxs < gys) ? 2 : 3)
                : (gxs < 0.f)               ? ((-gys < -gxs) ? 4 : 5)
                : (gys < 0.f)               ? ((gxs < -gys) ? 6 : 7)
                : 0;
        int b8 = (bin + 2) & 7;

        int dy = c_dy[b8], dx = c_dx[b8];
        int step = dy * SPITCH + dx;
        float f = 0.f, w = 0.f;
#pragma unroll
        for (int r = 1; r <= 6; r++) {
            f = fmaxf(f, t0[-step * r]);
            w = fmaxf(w, t0[ step * r]);
        }
        float mn = fminf(f, w), mx = fmaxf(f, w);
        float ratio = __fdividef(mn, mx + EPSV);
        float x0 = t0[0];
        float em = fminf(fmaxf(x0 * (1.f - ratio), 0.f), 1.f);

        size_t o = (size_t)b * HW + (size_t)(by + ly) * W + (bx + l64);
        __stcs(&emap[o], em);
        if (binsf) __stcs(&binsf[o], (float)b8);
        if (xnout) __stcs(&xnout[o], x0);
    }
}

// ---------------- launch ----------------
extern "C" void kernel_launch(void* const* d_in, const int* in_sizes, int n_in,
                              void* d_out, int out_size) {
    const float* x = (const float*)d_in[0];
    float* out = (float*)d_out;
    const size_t N = (size_t)BATCH * HW;

    float* emap  = out;
    float* binsf = ((size_t)out_size >= 2 * N) ? out + N : nullptr;
    float* xnout = ((size_t)out_size >= 3 * N) ? out + 2 * N : nullptr;

    k_zero<<<256, 256>>>();
    k_bounds<<<BATCH, 1024>>>(x);
    k_qhist<<<dim3(64, BATCH), 256>>>(x);
    k_qsum<<<512, 256>>>();
    k_qfinal<<<BATCH, 512>>>();
    k_rescue<<<BATCH, 256>>>(x);

    dim3 gf(W / TS, H / TS, BATCH);
    k_fused<<<gf, 512>>>(x, emap, binsf, xnout);
}